// round 1
// baseline (speedup 1.0000x reference)
#include <cuda_runtime.h>
#include <cstdint>

#define RTOT   32768
#define LSEQ   4096
#define NBATCH 8
#define DMODEL 128
#define DPROJ  648
#define DINNER 256
#define CONVD  384
#define NH     8
#define HD     32
#define CH     32

// ---------------- scratch (device globals: no allocation allowed) ----------
__device__ float g_xn [RTOT * DMODEL];          // 16 MB  normalized input
__device__ float g_zx [(size_t)RTOT * DPROJ];   // 85 MB  in_proj output (z | xBC | dt)
__device__ float g_xc [RTOT * CONVD];           // 50 MB  silu(conv(xBC))  (xs | B | C)
__device__ float g_dtb[RTOT * NH];              //  1 MB  softplus(dt + bias)
__device__ float g_y  [RTOT * DINNER];          // 33 MB  SSM output (incl. D skip)
__device__ float g_g  [RTOT * DINNER];          // 33 MB  gated+normalized
// ---------------------------------------------------------------------------

// packed fp32x2 helpers (full-precision fp32 FMA, 2 lanes/instr -> 128 FMA/cyc/SM)
static __device__ __forceinline__ unsigned long long fma2(unsigned long long a,
                                                          unsigned long long b,
                                                          unsigned long long c) {
    unsigned long long d;
    asm("fma.rn.f32x2 %0, %1, %2, %3;" : "=l"(d) : "l"(a), "l"(b), "l"(c));
    return d;
}
static __device__ __forceinline__ unsigned long long mul2(unsigned long long a,
                                                          unsigned long long b) {
    unsigned long long d;
    asm("mul.rn.f32x2 %0, %1, %2;" : "=l"(d) : "l"(a), "l"(b));
    return d;
}
static __device__ __forceinline__ unsigned long long pack2(float v) {
    unsigned long long r;
    asm("mov.b64 %0, {%1, %1};" : "=l"(r) : "f"(v));
    return r;
}
static __device__ __forceinline__ float lohi_sum(unsigned long long v) {
    float lo, hi;
    asm("mov.b64 {%0, %1}, %2;" : "=f"(lo), "=f"(hi) : "l"(v));
    return lo + hi;
}

// ---------------- K0: RMSNorm of x over DMODEL=128 (1 warp / row) ----------
__global__ void k_rmsnorm(const float* __restrict__ x, const float* __restrict__ w) {
    int row  = blockIdx.x * 8 + (threadIdx.x >> 5);
    int lane = threadIdx.x & 31;
    float4 v = ((const float4*)(x + (size_t)row * DMODEL))[lane];
    float ss = v.x * v.x + v.y * v.y + v.z * v.z + v.w * v.w;
#pragma unroll
    for (int o = 16; o; o >>= 1) ss += __shfl_xor_sync(0xffffffffu, ss, o);
    float sc = rsqrtf(ss * (1.f / DMODEL) + 1e-5f);
    float4 wv = ((const float4*)w)[lane];
    float4 o4;
    o4.x = v.x * sc * wv.x; o4.y = v.y * sc * wv.y;
    o4.z = v.z * sc * wv.z; o4.w = v.w * sc * wv.w;
    ((float4*)(g_xn + (size_t)row * DMODEL))[lane] = o4;
}

// ---------------- K1: in_proj GEMM  [R,128] @ [128,648]^T  (f32x2) ---------
// tile 64x64, K=128; strided microtile (rows ty+16i, cols tx+16j) for
// conflict-free LDS.64 (row stride 130 words -> bank stride 2).
__global__ void k_inproj(const float* __restrict__ W) {
    extern __shared__ float sm[];
    float* As = sm;             // [64][130]
    float* Bs = sm + 64 * 130;  // [64][130]
    int tid = threadIdx.x;
    int rowBase = blockIdx.x * 64;
    int colBase = blockIdx.y * 64;
    for (int i = tid; i < 64 * 64; i += 256) {
        int r = i >> 6, c2 = i & 63;
        *(float2*)&As[r * 130 + c2 * 2] =
            *(const float2*)&g_xn[(size_t)(rowBase + r) * DMODEL + c2 * 2];
        int wc = colBase + r;
        float2 bv = make_float2(0.f, 0.f);
        if (wc < DPROJ) bv = *(const float2*)&W[(size_t)wc * DMODEL + c2 * 2];
        *(float2*)&Bs[r * 130 + c2 * 2] = bv;
    }
    __syncthreads();
    int ty = tid >> 4, tx = tid & 15;
    unsigned long long acc[4][4];
#pragma unroll
    for (int i = 0; i < 4; i++)
#pragma unroll
        for (int j = 0; j < 4; j++) acc[i][j] = 0ull;
#pragma unroll 8
    for (int k = 0; k < 128; k += 2) {
        unsigned long long a[4], b[4];
#pragma unroll
        for (int i = 0; i < 4; i++)
            a[i] = *(const unsigned long long*)&As[(ty + 16 * i) * 130 + k];
#pragma unroll
        for (int j = 0; j < 4; j++)
            b[j] = *(const unsigned long long*)&Bs[(tx + 16 * j) * 130 + k];
#pragma unroll
        for (int i = 0; i < 4; i++)
#pragma unroll
            for (int j = 0; j < 4; j++) acc[i][j] = fma2(a[i], b[j], acc[i][j]);
    }
#pragma unroll
    for (int i = 0; i < 4; i++) {
        int r = rowBase + ty + 16 * i;
#pragma unroll
        for (int j = 0; j < 4; j++) {
            int c = colBase + tx + 16 * j;
            if (c < DPROJ) g_zx[(size_t)r * DPROJ + c] = lohi_sum(acc[i][j]);
        }
    }
}

// ---------------- K2: causal depthwise conv(K=4)+SiLU, softplus(dt) --------
__global__ void k_conv(const float* __restrict__ cw, const float* __restrict__ cb,
                       const float* __restrict__ dtb) {
    int r = blockIdx.x;
    int t = r & (LSEQ - 1);
    int tid = threadIdx.x;
#pragma unroll
    for (int cc = 0; cc < 3; cc++) {
        int c = tid + cc * 128;
        float acc = cb[c];
#pragma unroll
        for (int k = 0; k < 4; k++) {
            int tt = t - 3 + k;
            if (tt >= 0)
                acc += g_zx[(size_t)(r - 3 + k) * DPROJ + 256 + c] * cw[c * 4 + k];
        }
        g_xc[(size_t)r * CONVD + c] = acc / (1.f + __expf(-acc));  // silu
    }
    if (tid < NH) {
        float v = g_zx[(size_t)r * DPROJ + 640 + tid] + dtb[tid];
        g_dtb[(size_t)r * NH + tid] = (v > 20.f) ? v : log1pf(__expf(v));
    }
}

// ---------------- K3: SSM scan. 128 blocks = (b, h, p-half) ----------------
// 128 threads: pl=t/8 (p in half), nj=t&7 -> 8 states/thread packed in 4 u64.
// n-partition {4nj..4nj+3} U {32+4nj..35+4nj}: LDS.128 conflict-free.
// double-buffered 32-step chunks, staged global->reg->smem.
__global__ void k_scan(const float* __restrict__ A_log, const float* __restrict__ Dp) {
    __shared__ __align__(16) float sx [2][CH][16];
    __shared__ __align__(16) float sbc[2][CH][128];
    __shared__              float sdt[2][CH];
    __shared__ __align__(16) float sy [2][CH][16];

    int bx = blockIdx.x;
    int b  = bx >> 4;
    int h  = (bx >> 1) & 7;
    int ph = bx & 1;
    int t  = threadIdx.x;
    int pl = t >> 3;
    int nj = t & 7;
    float A  = -__expf(A_log[h]);
    float Dh = Dp[h];
    int xcol = h * HD + ph * 16;
    int brow = b * LSEQ;

    // preload chunk 0
    for (int i = t; i < CH * 36; i += 128) {
        int step = i / 36, j = i - step * 36;
        int col = (j < 4) ? (xcol + j * 4) : (256 + (j - 4) * 4);
        float4 v = *(const float4*)&g_xc[(size_t)(brow + step) * CONVD + col];
        if (j < 4) *(float4*)&sx[0][step][j * 4] = v;
        else       *(float4*)&sbc[0][step][(j - 4) * 4] = v;
    }
    if (t < CH) sdt[0][t] = g_dtb[(size_t)(brow + t) * NH + h];
    __syncthreads();

    unsigned long long h2[4] = {0ull, 0ull, 0ull, 0ull};
    const int nchunks = LSEQ / CH;  // 128
    for (int c = 0; c < nchunks; ++c) {
        int cur = c & 1;
        float4 st[9];
        float stdt = 0.f;
        bool more = (c + 1 < nchunks);
        if (more) {  // stage next chunk into registers (overlaps with compute)
            int r0 = brow + (c + 1) * CH;
#pragma unroll
            for (int i = 0; i < 9; i++) {
                int q = i * 128 + t;
                int step = q / 36, j = q - step * 36;
                int col = (j < 4) ? (xcol + j * 4) : (256 + (j - 4) * 4);
                st[i] = *(const float4*)&g_xc[(size_t)(r0 + step) * CONVD + col];
            }
            if (t < CH) stdt = g_dtb[(size_t)(brow + (c + 1) * CH + t) * NH + h];
        }
        // compute 32 steps
#pragma unroll 4
        for (int s = 0; s < CH; s++) {
            float dtv = sdt[cur][s];
            float dA  = __expf(dtv * A);
            float xv  = sx[cur][s][pl];
            unsigned long long dA2 = pack2(dA);
            unsigned long long sx2 = pack2(dtv * xv);
            const float* row = &sbc[cur][s][0];
            ulonglong2 B0 = *(const ulonglong2*)(row + 4 * nj);
            ulonglong2 B1 = *(const ulonglong2*)(row + 32 + 4 * nj);
            ulonglong2 C0 = *(const ulonglong2*)(row + 64 + 4 * nj);
            ulonglong2 C1 = *(const ulonglong2*)(row + 96 + 4 * nj);
            h2[0] = fma2(h2[0], dA2, mul2(sx2, B0.x));
            h2[1] = fma2(h2[1], dA2, mul2(sx2, B0.y));
            h2[2] = fma2(h2[2], dA2, mul2(sx2, B1.x));
            h2[3] = fma2(h2[3], dA2, mul2(sx2, B1.y));
            unsigned long long y2 = mul2(h2[0], C0.x);
            y2 = fma2(h2[1], C0.y, y2);
            y2 = fma2(h2[2], C1.x, y2);
            y2 = fma2(h2[3], C1.y, y2);
            float y = lohi_sum(y2);
            y += __shfl_xor_sync(0xffffffffu, y, 1);
            y += __shfl_xor_sync(0xffffffffu, y, 2);
            y += __shfl_xor_sync(0xffffffffu, y, 4);
            if (nj == 0) sy[cur][s][pl] = y + Dh * xv;  // D skip folded in
        }
        if (more) {  // commit staged regs to the other buffer
            int nxt = cur ^ 1;
#pragma unroll
            for (int i = 0; i < 9; i++) {
                int q = i * 128 + t;
                int step = q / 36, j = q - step * 36;
                if (j < 4) *(float4*)&sx[nxt][step][j * 4] = st[i];
                else       *(float4*)&sbc[nxt][step][(j - 4) * 4] = st[i];
            }
            if (t < CH) sdt[nxt][t] = stdt;
        }
        __syncthreads();
        // coalesced flush of y chunk
        {
            int r0 = brow + c * CH;
            int step = t >> 2, jo = t & 3;
            *(float4*)&g_y[(size_t)(r0 + step) * DINNER + xcol + jo * 4] =
                *(const float4*)&sy[cur][step][jo * 4];
        }
    }
}

// ---------------- K4a: gating + gated RMSNorm over DINNER=256 --------------
__global__ void k_gate(const float* __restrict__ gw) {
    int r = blockIdx.x;
    int i = threadIdx.x;
    float yv = g_y[(size_t)r * DINNER + i];
    float zv = g_zx[(size_t)r * DPROJ + i];
    float gv = yv * (zv / (1.f + __expf(-zv)));
    float ss = gv * gv;
#pragma unroll
    for (int o = 16; o; o >>= 1) ss += __shfl_xor_sync(0xffffffffu, ss, o);
    __shared__ float red[8];
    if ((i & 31) == 0) red[i >> 5] = ss;
    __syncthreads();
    float tot = red[0] + red[1] + red[2] + red[3] + red[4] + red[5] + red[6] + red[7];
    float sc = rsqrtf(tot * (1.f / DINNER) + 1e-5f);
    g_g[(size_t)r * DINNER + i] = gv * sc * gw[i];
}

// ---------------- K4b: out_proj GEMM [R,256]@[256,128]^T + residual --------
__global__ void k_outproj(const float* __restrict__ W, const float* __restrict__ x,
                          float* __restrict__ out) {
    extern __shared__ float sm[];
    float* As = sm;
    float* Bs = sm + 64 * 130;
    int tid = threadIdx.x;
    int rowBase = blockIdx.x * 64;
    int colBase = blockIdx.y * 64;
    int ty = tid >> 4, tx = tid & 15;
    unsigned long long acc[4][4];
#pragma unroll
    for (int i = 0; i < 4; i++)
#pragma unroll
        for (int j = 0; j < 4; j++) acc[i][j] = 0ull;
#pragma unroll
    for (int kh = 0; kh < 2; ++kh) {
        if (kh) __syncthreads();
        for (int i = tid; i < 64 * 64; i += 256) {
            int r = i >> 6, c2 = i & 63;
            *(float2*)&As[r * 130 + c2 * 2] =
                *(const float2*)&g_g[(size_t)(rowBase + r) * DINNER + kh * 128 + c2 * 2];
            *(float2*)&Bs[r * 130 + c2 * 2] =
                *(const float2*)&W[(size_t)(colBase + r) * DINNER + kh * 128 + c2 * 2];
        }
        __syncthreads();
#pragma unroll 8
        for (int k = 0; k < 128; k += 2) {
            unsigned long long a[4], b[4];
#pragma unroll
            for (int i = 0; i < 4; i++)
                a[i] = *(const unsigned long long*)&As[(ty + 16 * i) * 130 + k];
#pragma unroll
            for (int j = 0; j < 4; j++)
                b[j] = *(const unsigned long long*)&Bs[(tx + 16 * j) * 130 + k];
#pragma unroll
            for (int i = 0; i < 4; i++)
#pragma unroll
                for (int j = 0; j < 4; j++) acc[i][j] = fma2(a[i], b[j], acc[i][j]);
        }
    }
#pragma unroll
    for (int i = 0; i < 4; i++) {
        int r = rowBase + ty + 16 * i;
#pragma unroll
        for (int j = 0; j < 4; j++) {
            int c = colBase + tx + 16 * j;
            out[(size_t)r * DMODEL + c] =
                lohi_sum(acc[i][j]) + x[(size_t)r * DMODEL + c];
        }
    }
}

extern "C" void kernel_launch(void* const* d_in, const int* in_sizes, int n_in,
                              void* d_out, int out_size) {
    const float* x          = (const float*)d_in[0];
    const float* norm_w     = (const float*)d_in[1];
    const float* in_proj_w  = (const float*)d_in[2];
    const float* conv_w     = (const float*)d_in[3];
    const float* conv_b     = (const float*)d_in[4];
    const float* dt_bias    = (const float*)d_in[5];
    const float* A_log      = (const float*)d_in[6];
    const float* D          = (const float*)d_in[7];
    const float* gnorm_w    = (const float*)d_in[8];
    const float* out_proj_w = (const float*)d_in[9];
    float* out = (float*)d_out;

    const int gemm_smem = 2 * 64 * 130 * 4;  // 66560 B
    cudaFuncSetAttribute(k_inproj,  cudaFuncAttributeMaxDynamicSharedMemorySize, gemm_smem);
    cudaFuncSetAttribute(k_outproj, cudaFuncAttributeMaxDynamicSharedMemorySize, gemm_smem);

    k_rmsnorm<<<RTOT / 8, 256>>>(x, norm_w);
    k_inproj<<<dim3(RTOT / 64, (DPROJ + 63) / 64), 256, gemm_smem>>>(in_proj_w);
    k_conv<<<RTOT, 128>>>(conv_w, conv_b, dt_bias);
    k_scan<<<128, 128>>>(A_log, D);
    k_gate<<<RTOT, 256>>>(gnorm_w);
    k_outproj<<<dim3(RTOT / 64, 2), 256, gemm_smem>>>(out_proj_w, x, out);
}

// round 3
// speedup vs baseline: 1.6444x; 1.6444x over previous
#include <cuda_runtime.h>
#include <cstdint>

#define RTOT   32768
#define LSEQ   4096
#define NBATCH 8
#define DMODEL 128
#define DPROJ  648
#define DINNER 256
#define CONVD  384
#define NH     8
#define HD     32
#define QC     64          // SSD chunk length
#define NCHK   (LSEQ/QC)   // 64 chunks per sequence
#define NCID   (NBATCH*NH*NCHK)  // 4096 chunk instances

// ---------------- scratch (device globals: no allocation allowed) ----------
__device__ __align__(16) float g_xn [RTOT * DMODEL];
__device__ __align__(16) float g_zx [(size_t)RTOT * DPROJ];
__device__ __align__(16) float g_xc [RTOT * CONVD];
__device__ __align__(16) float g_dtb[RTOT * NH];
__device__ __align__(16) float g_y  [RTOT * DINNER];
__device__ __align__(16) float g_g  [RTOT * DINNER];
__device__ __align__(16) float g_U  [(size_t)NCID * 2048];
__device__ __align__(16) float g_hs [(size_t)NCID * 2048];
__device__ __align__(16) float g_S  [(size_t)NCID * QC];
__device__ __align__(16) float g_T  [NCID];
// ---------------------------------------------------------------------------

// packed fp32x2 helpers (full-precision fp32 FMA, 2 lanes/instr)
static __device__ __forceinline__ unsigned long long fma2(unsigned long long a,
                                                          unsigned long long b,
                                                          unsigned long long c) {
    unsigned long long d;
    asm("fma.rn.f32x2 %0, %1, %2, %3;" : "=l"(d) : "l"(a), "l"(b), "l"(c));
    return d;
}
static __device__ __forceinline__ unsigned long long pack2(float v) {
    unsigned long long r;
    asm("mov.b64 %0, {%1, %1};" : "=l"(r) : "f"(v));
    return r;
}
static __device__ __forceinline__ float lohi_sum(unsigned long long v) {
    float lo, hi;
    asm("mov.b64 {%0, %1}, %2;" : "=f"(lo), "=f"(hi) : "l"(v));
    return lo + hi;
}

// ---------------- K0: RMSNorm of x over DMODEL=128 (1 warp / row) ----------
__global__ void k_rmsnorm(const float* __restrict__ x, const float* __restrict__ w) {
    int row  = blockIdx.x * 8 + (threadIdx.x >> 5);
    int lane = threadIdx.x & 31;
    float4 v = ((const float4*)(x + (size_t)row * DMODEL))[lane];
    float ss = v.x * v.x + v.y * v.y + v.z * v.z + v.w * v.w;
#pragma unroll
    for (int o = 16; o; o >>= 1) ss += __shfl_xor_sync(0xffffffffu, ss, o);
    float sc = rsqrtf(ss * (1.f / DMODEL) + 1e-5f);
    float4 wv = ((const float4*)w)[lane];
    float4 o4;
    o4.x = v.x * sc * wv.x; o4.y = v.y * sc * wv.y;
    o4.z = v.z * sc * wv.z; o4.w = v.w * sc * wv.w;
    ((float4*)(g_xn + (size_t)row * DMODEL))[lane] = o4;
}

// ---------------- K1: in_proj GEMM  [R,128] @ [128,648]^T  (f32x2) ---------
__global__ void k_inproj(const float* __restrict__ W) {
    extern __shared__ float sm[];
    float* As = sm;             // [64][130]
    float* Bs = sm + 64 * 130;  // [64][130]
    int tid = threadIdx.x;
    int rowBase = blockIdx.x * 64;
    int colBase = blockIdx.y * 64;
    for (int i = tid; i < 64 * 64; i += 256) {
        int r = i >> 6, c2 = i & 63;
        *(float2*)&As[r * 130 + c2 * 2] =
            *(const float2*)&g_xn[(size_t)(rowBase + r) * DMODEL + c2 * 2];
        int wc = colBase + r;
        float2 bv = make_float2(0.f, 0.f);
        if (wc < DPROJ) bv = *(const float2*)&W[(size_t)wc * DMODEL + c2 * 2];
        *(float2*)&Bs[r * 130 + c2 * 2] = bv;
    }
    __syncthreads();
    int ty = tid >> 4, tx = tid & 15;
    unsigned long long acc[4][4];
#pragma unroll
    for (int i = 0; i < 4; i++)
#pragma unroll
        for (int j = 0; j < 4; j++) acc[i][j] = 0ull;
#pragma unroll 8
    for (int k = 0; k < 128; k += 2) {
        unsigned long long a[4], b[4];
#pragma unroll
        for (int i = 0; i < 4; i++)
            a[i] = *(const unsigned long long*)&As[(ty + 16 * i) * 130 + k];
#pragma unroll
        for (int j = 0; j < 4; j++)
            b[j] = *(const unsigned long long*)&Bs[(tx + 16 * j) * 130 + k];
#pragma unroll
        for (int i = 0; i < 4; i++)
#pragma unroll
            for (int j = 0; j < 4; j++) acc[i][j] = fma2(a[i], b[j], acc[i][j]);
    }
#pragma unroll
    for (int i = 0; i < 4; i++) {
        int r = rowBase + ty + 16 * i;
#pragma unroll
        for (int j = 0; j < 4; j++) {
            int c = colBase + tx + 16 * j;
            if (c < DPROJ) g_zx[(size_t)r * DPROJ + c] = lohi_sum(acc[i][j]);
        }
    }
}

// ---------------- K2: causal depthwise conv(K=4)+SiLU, softplus(dt) --------
__global__ void k_conv(const float* __restrict__ cw, const float* __restrict__ cb,
                       const float* __restrict__ dtb) {
    int r = blockIdx.x;
    int t = r & (LSEQ - 1);
    int tid = threadIdx.x;
#pragma unroll
    for (int cc = 0; cc < 3; cc++) {
        int c = tid + cc * 128;
        float acc = cb[c];
#pragma unroll
        for (int k = 0; k < 4; k++) {
            int tt = t - 3 + k;
            if (tt >= 0)
                acc += g_zx[(size_t)(r - 3 + k) * DPROJ + 256 + c] * cw[c * 4 + k];
        }
        g_xc[(size_t)r * CONVD + c] = acc / (1.f + __expf(-acc));  // silu
    }
    if (tid < NH) {
        float v = g_zx[(size_t)r * DPROJ + 640 + tid] + dtb[tid];
        g_dtb[(size_t)r * NH + tid] = (v > 20.f) ? v : log1pf(__expf(v));
    }
}

// ---------------- SSD pass A: per-chunk cumsum + state contribution U ------
// grid 4096 = (b*8+h)*64 + c.  U[p][n] = sum_s exp(T - S_s) dt_s x[s][p] B[s][n]
__global__ void __launch_bounds__(128) k_ssd_a(const float* __restrict__ A_log) {
    __shared__ __align__(16) float Bs[64 * 68];
    __shared__ __align__(16) float Xs[64 * 36];
    __shared__ float sdt[64], sS[64], ssc[64];
    int tid = threadIdx.x;
    int cid = blockIdx.x;
    int bh = cid >> 6, c = cid & 63;
    int b = bh >> 3, h = bh & 7;
    int r0 = b * LSEQ + c * QC;
    float A = -__expf(A_log[h]);
    if (tid < 64) sdt[tid] = g_dtb[(size_t)(r0 + tid) * NH + h];
    for (int i = tid; i < 1024; i += 128) {
        int s = i >> 4, q = i & 15;
        *(float4*)&Bs[s * 68 + q * 4] =
            *(const float4*)&g_xc[(size_t)(r0 + s) * CONVD + 256 + q * 4];
    }
    __syncthreads();
    if (tid < 64) {
        float v = sdt[tid] * A;
#pragma unroll
        for (int o = 1; o < 32; o <<= 1) {
            float u = __shfl_up_sync(0xffffffffu, v, o);
            if ((tid & 31) >= o) v += u;
        }
        sS[tid] = v;
    }
    __syncthreads();
    if (tid >= 32 && tid < 64) sS[tid] += sS[31];
    __syncthreads();
    float T = sS[63];
    if (tid < 64) {
        float sv = sS[tid];
        g_S[(size_t)cid * QC + tid] = sv;
        ssc[tid] = __expf(T - sv) * sdt[tid];
    }
    if (tid == 0) g_T[cid] = T;
    __syncthreads();
    for (int i = tid; i < 512; i += 128) {
        int s = i >> 3, q = i & 7;
        float4 v = *(const float4*)&g_xc[(size_t)(r0 + s) * CONVD + h * HD + q * 4];
        float sc = ssc[s];
        v.x *= sc; v.y *= sc; v.z *= sc; v.w *= sc;
        *(float4*)&Xs[s * 36 + q * 4] = v;
    }
    __syncthreads();
    int ty = tid >> 4, tx = tid & 15;
    unsigned long long acc[4][2] = {};
#pragma unroll 4
    for (int s = 0; s < 64; s++) {
        unsigned long long b0 = *(const unsigned long long*)&Bs[s * 68 + 2 * tx];
        unsigned long long b1 = *(const unsigned long long*)&Bs[s * 68 + 2 * tx + 32];
#pragma unroll
        for (int i = 0; i < 4; i++) {
            unsigned long long xa = pack2(Xs[s * 36 + ty + 8 * i]);
            acc[i][0] = fma2(xa, b0, acc[i][0]);
            acc[i][1] = fma2(xa, b1, acc[i][1]);
        }
    }
    size_t ub = (size_t)cid * 2048;
#pragma unroll
    for (int i = 0; i < 4; i++) {
        int p = ty + 8 * i;
        *(unsigned long long*)&g_U[ub + p * 64 + 2 * tx]      = acc[i][0];
        *(unsigned long long*)&g_U[ub + p * 64 + 2 * tx + 32] = acc[i][1];
    }
}

// ---------------- SSD pass B: chunk-level state scan (64 serial steps) -----
// grid 64 = (b,h); h_start[c+1] = exp(T_c) * h_start[c] + U_c  (elementwise)
__global__ void k_ssd_b() {
    int bh = blockIdx.x;
    int tid = threadIdx.x;  // 256
    size_t base = (size_t)bh * NCHK;
    float4 h0 = make_float4(0.f, 0.f, 0.f, 0.f), h1 = h0;
    float4 u0 = *(const float4*)&g_U[base * 2048 + tid * 4];
    float4 u1 = *(const float4*)&g_U[base * 2048 + 1024 + tid * 4];
    for (int c = 0; c < NCHK; c++) {
        size_t off = (base + c) * 2048;
        *(float4*)&g_hs[off + tid * 4]        = h0;
        *(float4*)&g_hs[off + 1024 + tid * 4] = h1;
        float e = __expf(g_T[base + c]);
        float4 n0 = make_float4(0.f, 0.f, 0.f, 0.f), n1 = n0;
        if (c + 1 < NCHK) {
            n0 = *(const float4*)&g_U[off + 2048 + tid * 4];
            n1 = *(const float4*)&g_U[off + 2048 + 1024 + tid * 4];
        }
        h0.x = e * h0.x + u0.x; h0.y = e * h0.y + u0.y;
        h0.z = e * h0.z + u0.z; h0.w = e * h0.w + u0.w;
        h1.x = e * h1.x + u1.x; h1.y = e * h1.y + u1.y;
        h1.z = e * h1.z + u1.z; h1.w = e * h1.w + u1.w;
        u0 = n0; u1 = n1;
    }
}

// ---------------- SSD pass C: per-chunk output -----------------------------
// Y[t][p] = sum_{s<=t} exp(S_t-S_s) dt_s (C_t.B_s) x[s][p]
//         + exp(S_t) * (C_t . h_start[p,:]) + D_h * x[t][p]
// smem rows padded to 68 floats (272B = 17*16) -> float4-aligned rows AND
// conflict-free LDS.64 columns (68 mod 64 = 4 word-pairs per row step).
__global__ void __launch_bounds__(256, 2) k_ssd_c(const float* __restrict__ Dp) {
    extern __shared__ float sm[];
    float* Cs  = sm;             // [64][68]  (t, n)
    float* Bm  = sm + 4352;      // [64][68]  B (s,n), later reused as M (t,s)
    float* XT  = sm + 8704;      // [32][68]  x transposed (p, s)
    float* hsm = sm + 10880;     // [32][68]  h_start (p, n)
    float* Ssm = sm + 13056;     // [64]
    float* dts = sm + 13120;     // [64]
    int tid = threadIdx.x;
    int cid = blockIdx.x;
    int bh = cid >> 6, c = cid & 63;
    int b = bh >> 3, h = bh & 7;
    int r0 = b * LSEQ + c * QC;
    float Dh = Dp[h];

    for (int i = tid; i < 1024; i += 256) {
        int s = i >> 4, q = i & 15;
        *(float4*)&Cs[s * 68 + q * 4] =
            *(const float4*)&g_xc[(size_t)(r0 + s) * CONVD + 320 + q * 4];
        *(float4*)&Bm[s * 68 + q * 4] =
            *(const float4*)&g_xc[(size_t)(r0 + s) * CONVD + 256 + q * 4];
    }
    for (int i = tid; i < 512; i += 256) {
        int s = i >> 3, q = i & 7;
        float4 v = *(const float4*)&g_xc[(size_t)(r0 + s) * CONVD + h * HD + q * 4];
        XT[(q * 4 + 0) * 68 + s] = v.x;
        XT[(q * 4 + 1) * 68 + s] = v.y;
        XT[(q * 4 + 2) * 68 + s] = v.z;
        XT[(q * 4 + 3) * 68 + s] = v.w;
    }
    for (int i = tid; i < 512; i += 256) {
        int p = i >> 4, q = i & 15;
        *(float4*)&hsm[p * 68 + q * 4] =
            *(const float4*)&g_hs[(size_t)cid * 2048 + i * 4];
    }
    if (tid < 64) {
        Ssm[tid] = g_S[(size_t)cid * QC + tid];
        dts[tid] = g_dtb[(size_t)(r0 + tid) * NH + h];
    }
    __syncthreads();

    int ty = tid >> 4, tx = tid & 15;
    // --- G = C B^T  (f32x2 over n pairs) ---
    unsigned long long g2[4][4] = {};
#pragma unroll 4
    for (int kp = 0; kp < 32; kp++) {
        unsigned long long a[4], bb[4];
#pragma unroll
        for (int i = 0; i < 4; i++)
            a[i] = *(const unsigned long long*)&Cs[(ty + 16 * i) * 68 + 2 * kp];
#pragma unroll
        for (int j = 0; j < 4; j++)
            bb[j] = *(const unsigned long long*)&Bm[(tx + 16 * j) * 68 + 2 * kp];
#pragma unroll
        for (int i = 0; i < 4; i++)
#pragma unroll
            for (int j = 0; j < 4; j++) g2[i][j] = fma2(a[i], bb[j], g2[i][j]);
    }
    float Gv[4][4];
#pragma unroll
    for (int i = 0; i < 4; i++)
#pragma unroll
        for (int j = 0; j < 4; j++) Gv[i][j] = lohi_sum(g2[i][j]);
    __syncthreads();  // all B reads done; Bm becomes M

    // --- M[t][s] = mask(s<=t) * G * exp(S_t - S_s) * dt_s ---
#pragma unroll
    for (int i = 0; i < 4; i++) {
        int t = ty + 16 * i;
        float St = Ssm[t];
#pragma unroll
        for (int j = 0; j < 4; j++) {
            int s = tx + 16 * j;
            float m = 0.f;
            if (s <= t) m = Gv[i][j] * __expf(St - Ssm[s]) * dts[s];
            Bm[t * 68 + s] = m;
        }
    }
    __syncthreads();

    // --- Y = M @ X^T  +  exp(S_t) * (C @ h_start^T) ---
    unsigned long long yi[4][2] = {}, yo[4][2] = {};
#pragma unroll 2
    for (int sp = 0; sp < 32; sp++) {
        unsigned long long a[4], ca[4];
#pragma unroll
        for (int i = 0; i < 4; i++)
            a[i] = *(const unsigned long long*)&Bm[(ty + 16 * i) * 68 + 2 * sp];
        unsigned long long x0 = *(const unsigned long long*)&XT[tx * 68 + 2 * sp];
        unsigned long long x1 = *(const unsigned long long*)&XT[(tx + 16) * 68 + 2 * sp];
#pragma unroll
        for (int i = 0; i < 4; i++) {
            yi[i][0] = fma2(a[i], x0, yi[i][0]);
            yi[i][1] = fma2(a[i], x1, yi[i][1]);
        }
#pragma unroll
        for (int i = 0; i < 4; i++)
            ca[i] = *(const unsigned long long*)&Cs[(ty + 16 * i) * 68 + 2 * sp];
        unsigned long long h0 = *(const unsigned long long*)&hsm[tx * 68 + 2 * sp];
        unsigned long long h1 = *(const unsigned long long*)&hsm[(tx + 16) * 68 + 2 * sp];
#pragma unroll
        for (int i = 0; i < 4; i++) {
            yo[i][0] = fma2(ca[i], h0, yo[i][0]);
            yo[i][1] = fma2(ca[i], h1, yo[i][1]);
        }
    }
#pragma unroll
    for (int i = 0; i < 4; i++) {
        int t = ty + 16 * i;
        float et = __expf(Ssm[t]);
#pragma unroll
        for (int l = 0; l < 2; l++) {
            int p = tx + 16 * l;
            float yv = lohi_sum(yi[i][l]) + et * lohi_sum(yo[i][l])
                     + Dh * XT[p * 68 + t];
            g_y[(size_t)(r0 + t) * DINNER + h * HD + p] = yv;
        }
    }
}

// ---------------- K4a: gating + gated RMSNorm over DINNER=256 --------------
__global__ void k_gate(const float* __restrict__ gw) {
    int r = blockIdx.x;
    int i = threadIdx.x;
    float yv = g_y[(size_t)r * DINNER + i];
    float zv = g_zx[(size_t)r * DPROJ + i];
    float gv = yv * (zv / (1.f + __expf(-zv)));
    float ss = gv * gv;
#pragma unroll
    for (int o = 16; o; o >>= 1) ss += __shfl_xor_sync(0xffffffffu, ss, o);
    __shared__ float red[8];
    if ((i & 31) == 0) red[i >> 5] = ss;
    __syncthreads();
    float tot = red[0] + red[1] + red[2] + red[3] + red[4] + red[5] + red[6] + red[7];
    float sc = rsqrtf(tot * (1.f / DINNER) + 1e-5f);
    g_g[(size_t)r * DINNER + i] = gv * sc * gw[i];
}

// ---------------- K4b: out_proj GEMM [R,256]@[256,128]^T + residual --------
__global__ void k_outproj(const float* __restrict__ W, const float* __restrict__ x,
                          float* __restrict__ out) {
    extern __shared__ float sm[];
    float* As = sm;
    float* Bs = sm + 64 * 130;
    int tid = threadIdx.x;
    int rowBase = blockIdx.x * 64;
    int colBase = blockIdx.y * 64;
    int ty = tid >> 4, tx = tid & 15;
    unsigned long long acc[4][4];
#pragma unroll
    for (int i = 0; i < 4; i++)
#pragma unroll
        for (int j = 0; j < 4; j++) acc[i][j] = 0ull;
#pragma unroll
    for (int kh = 0; kh < 2; ++kh) {
        if (kh) __syncthreads();
        for (int i = tid; i < 64 * 64; i += 256) {
            int r = i >> 6, c2 = i & 63;
            *(float2*)&As[r * 130 + c2 * 2] =
                *(const float2*)&g_g[(size_t)(rowBase + r) * DINNER + kh * 128 + c2 * 2];
            *(float2*)&Bs[r * 130 + c2 * 2] =
                *(const float2*)&W[(size_t)(colBase + r) * DINNER + kh * 128 + c2 * 2];
        }
        __syncthreads();
#pragma unroll 8
        for (int k = 0; k < 128; k += 2) {
            unsigned long long a[4], b[4];
#pragma unroll
            for (int i = 0; i < 4; i++)
                a[i] = *(const unsigned long long*)&As[(ty + 16 * i) * 130 + k];
#pragma unroll
            for (int j = 0; j < 4; j++)
                b[j] = *(const unsigned long long*)&Bs[(tx + 16 * j) * 130 + k];
#pragma unroll
            for (int i = 0; i < 4; i++)
#pragma unroll
                for (int j = 0; j < 4; j++) acc[i][j] = fma2(a[i], b[j], acc[i][j]);
        }
    }
#pragma unroll
    for (int i = 0; i < 4; i++) {
        int r = rowBase + ty + 16 * i;
#pragma unroll
        for (int j = 0; j < 4; j++) {
            int c = colBase + tx + 16 * j;
            out[(size_t)r * DMODEL + c] =
                lohi_sum(acc[i][j]) + x[(size_t)r * DMODEL + c];
        }
    }
}

extern "C" void kernel_launch(void* const* d_in, const int* in_sizes, int n_in,
                              void* d_out, int out_size) {
    const float* x          = (const float*)d_in[0];
    const float* norm_w     = (const float*)d_in[1];
    const float* in_proj_w  = (const float*)d_in[2];
    const float* conv_w     = (const float*)d_in[3];
    const float* conv_b     = (const float*)d_in[4];
    const float* dt_bias    = (const float*)d_in[5];
    const float* A_log      = (const float*)d_in[6];
    const float* D          = (const float*)d_in[7];
    const float* gnorm_w    = (const float*)d_in[8];
    const float* out_proj_w = (const float*)d_in[9];
    float* out = (float*)d_out;

    const int gemm_smem = 2 * 64 * 130 * 4;  // 66560 B
    const int ssdc_smem = 13184 * 4;         // 52736 B
    cudaFuncSetAttribute(k_inproj,  cudaFuncAttributeMaxDynamicSharedMemorySize, gemm_smem);
    cudaFuncSetAttribute(k_outproj, cudaFuncAttributeMaxDynamicSharedMemorySize, gemm_smem);
    cudaFuncSetAttribute(k_ssd_c,   cudaFuncAttributeMaxDynamicSharedMemorySize, ssdc_smem);

    k_rmsnorm<<<RTOT / 8, 256>>>(x, norm_w);
    k_inproj<<<dim3(RTOT / 64, (DPROJ + 63) / 64), 256, gemm_smem>>>(in_proj_w);
    k_conv<<<RTOT, 128>>>(conv_w, conv_b, dt_bias);
    k_ssd_a<<<NCID, 128>>>(A_log);
    k_ssd_b<<<NBATCH * NH, 256>>>();
    k_ssd_c<<<NCID, 256, ssdc_smem>>>(D);
    k_gate<<<RTOT, 256>>>(gnorm_w);
    k_outproj<<<dim3(RTOT / 64, 2), 256, gemm_smem>>>(out_proj_w, x, out);
}

// round 5
// speedup vs baseline: 1.9783x; 1.2030x over previous
#include <cuda_runtime.h>
#include <cuda_bf16.h>
#include <cstdint>

#define RTOT   32768
#define LSEQ   4096
#define NBATCH 8
#define DMODEL 128
#define DPROJ  648
#define DINNER 256
#define CONVD  384
#define NH     8
#define HD     32
#define QC     64
#define NCHK   (LSEQ/QC)
#define NCID   (NBATCH*NH*NCHK)

// ---------------- scratch (device globals) ----------------------------------
__device__ __align__(16) float g_xn [RTOT * DMODEL];          // fp32 rmsnorm(x)
__device__ __align__(16) float g_zx [(size_t)RTOT * DPROJ];
__device__ __align__(16) float g_xc [RTOT * CONVD];
__device__ __align__(16) float g_dtb[RTOT * NH];
__device__ __align__(16) float g_y  [RTOT * DINNER];
__device__ __align__(16) float g_U  [(size_t)NCID * 2048];
__device__ __align__(16) float g_hs [(size_t)NCID * 2048];
__device__ __align__(16) float g_S  [(size_t)NCID * QC];
__device__ __align__(16) float g_T  [NCID];
// bf16 split operands for tensor-core GEMMs (weights padded to 672 rows)
__device__ __align__(16) __nv_bfloat16 g_ah [RTOT * DMODEL];
__device__ __align__(16) __nv_bfloat16 g_al [RTOT * DMODEL];
__device__ __align__(16) __nv_bfloat16 g_wih[672 * DMODEL];
__device__ __align__(16) __nv_bfloat16 g_wil[672 * DMODEL];
__device__ __align__(16) __nv_bfloat16 g_gh [RTOT * DINNER];
__device__ __align__(16) __nv_bfloat16 g_gl [RTOT * DINNER];
__device__ __align__(16) __nv_bfloat16 g_woh[DMODEL * DINNER];
__device__ __align__(16) __nv_bfloat16 g_wol[DMODEL * DINNER];
// -----------------------------------------------------------------------------

// ---- fp32x2 helpers ----
static __device__ __forceinline__ unsigned long long fma2(unsigned long long a,
                                                          unsigned long long b,
                                                          unsigned long long c) {
    unsigned long long d;
    asm("fma.rn.f32x2 %0, %1, %2, %3;" : "=l"(d) : "l"(a), "l"(b), "l"(c));
    return d;
}
static __device__ __forceinline__ unsigned long long pack2(float v) {
    unsigned long long r;
    asm("mov.b64 %0, {%1, %1};" : "=l"(r) : "f"(v));
    return r;
}
static __device__ __forceinline__ float lohi_sum(unsigned long long v) {
    float lo, hi;
    asm("mov.b64 {%0, %1}, %2;" : "=f"(lo), "=f"(hi) : "l"(v));
    return lo + hi;
}

// ---- warp MMA helpers (sm_80+ portable) ----
static __device__ __forceinline__ uint32_t smem_u32(const void* p) {
    uint32_t a;
    asm("{ .reg .u64 t; cvta.to.shared.u64 t, %1; cvt.u32.u64 %0, t; }"
        : "=r"(a) : "l"(p));
    return a;
}
#define LDSM4(r, addr) \
    asm volatile("ldmatrix.sync.aligned.m8n8.x4.shared.b16 {%0,%1,%2,%3}, [%4];" \
        : "=r"((r)[0]), "=r"((r)[1]), "=r"((r)[2]), "=r"((r)[3]) : "r"(addr))
#define MMA16816(d, a, b0, b1) \
    asm volatile("mma.sync.aligned.m16n8k16.row.col.f32.bf16.bf16.f32 " \
        "{%0,%1,%2,%3}, {%4,%5,%6,%7}, {%8,%9}, {%0,%1,%2,%3};" \
        : "+f"((d)[0]), "+f"((d)[1]), "+f"((d)[2]), "+f"((d)[3]) \
        : "r"((a)[0]), "r"((a)[1]), "r"((a)[2]), "r"((a)[3]), "r"(b0), "r"(b1))

static __device__ __forceinline__ void split_bf16(float v, __nv_bfloat16& h,
                                                  __nv_bfloat16& l) {
    h = __float2bfloat16(v);
    l = __float2bfloat16(v - __bfloat162float(h));
}

// ---------------- K_w: one-shot weight split -------------------------------
__global__ void k_wsplit(const float* __restrict__ Wi, const float* __restrict__ Wo) {
    int idx = blockIdx.x * 256 + threadIdx.x;   // vec4 index
    const int NWI = DPROJ * DMODEL / 4;         // 20736
    const int NWO = DMODEL * DINNER / 4;        // 8192
    if (idx < NWI) {
        float4 v = ((const float4*)Wi)[idx];
        __nv_bfloat16 h[4], l[4];
        split_bf16(v.x, h[0], l[0]); split_bf16(v.y, h[1], l[1]);
        split_bf16(v.z, h[2], l[2]); split_bf16(v.w, h[3], l[3]);
        ((uint2*)g_wih)[idx] = *(uint2*)h;
        ((uint2*)g_wil)[idx] = *(uint2*)l;
    } else if (idx < NWI + NWO) {
        int j = idx - NWI;
        float4 v = ((const float4*)Wo)[j];
        __nv_bfloat16 h[4], l[4];
        split_bf16(v.x, h[0], l[0]); split_bf16(v.y, h[1], l[1]);
        split_bf16(v.z, h[2], l[2]); split_bf16(v.w, h[3], l[3]);
        ((uint2*)g_woh)[j] = *(uint2*)h;
        ((uint2*)g_wol)[j] = *(uint2*)l;
    }
}

// ---------------- K0: RMSNorm -> fp32 + bf16 hi/lo splits -------------------
__global__ void k_rmsnorm(const float* __restrict__ x, const float* __restrict__ w) {
    int row  = blockIdx.x * 8 + (threadIdx.x >> 5);
    int lane = threadIdx.x & 31;
    float4 v = ((const float4*)(x + (size_t)row * DMODEL))[lane];
    float ss = v.x * v.x + v.y * v.y + v.z * v.z + v.w * v.w;
#pragma unroll
    for (int o = 16; o; o >>= 1) ss += __shfl_xor_sync(0xffffffffu, ss, o);
    float sc = rsqrtf(ss * (1.f / DMODEL) + 1e-5f);
    float4 wv = ((const float4*)w)[lane];
    float4 o4;
    o4.x = v.x * sc * wv.x; o4.y = v.y * sc * wv.y;
    o4.z = v.z * sc * wv.z; o4.w = v.w * sc * wv.w;
    ((float4*)(g_xn + (size_t)row * DMODEL))[lane] = o4;
    __nv_bfloat16 h[4], l[4];
    split_bf16(o4.x, h[0], l[0]); split_bf16(o4.y, h[1], l[1]);
    split_bf16(o4.z, h[2], l[2]); split_bf16(o4.w, h[3], l[3]);
    ((uint2*)(g_ah + (size_t)row * DMODEL))[lane] = *(uint2*)h;
    ((uint2*)(g_al + (size_t)row * DMODEL))[lane] = *(uint2*)l;
}

// ---------------- K1: in_proj GEMM via HMMA bf16x3, tile 128x96, K=128 ------
// smem element offsets (bf16, row pitch 136)
#define IP_AH 0
#define IP_AL 17408
#define IP_BH 34816
#define IP_BL 47872
#define IP_TOT 60928   // elements -> 121856 bytes
__global__ void __launch_bounds__(256, 1) k_inproj_mma() {
    extern __shared__ __align__(16) __nv_bfloat16 smb[];
    int tid = threadIdx.x, wid = tid >> 5, lane = tid & 31;
    int rowBase = blockIdx.x * 128;
    int colBase = blockIdx.y * 96;

    for (int i = tid; i < 2048; i += 256) {
        int r = i >> 4, c = (i & 15) << 3;
        *(uint4*)&smb[IP_AH + r * 136 + c] =
            *(const uint4*)(g_ah + (size_t)(rowBase + r) * DMODEL + c);
        *(uint4*)&smb[IP_AL + r * 136 + c] =
            *(const uint4*)(g_al + (size_t)(rowBase + r) * DMODEL + c);
    }
    for (int i = tid; i < 1536; i += 256) {
        int r = i >> 4, c = (i & 15) << 3;
        *(uint4*)&smb[IP_BH + r * 136 + c] =
            *(const uint4*)(g_wih + (size_t)(colBase + r) * DMODEL + c);
        *(uint4*)&smb[IP_BL + r * 136 + c] =
            *(const uint4*)(g_wil + (size_t)(colBase + r) * DMODEL + c);
    }
    __syncthreads();

    uint32_t sb = smem_u32(smb);
    int mw = wid & 3, nw = wid >> 2;
    int arow = mw * 32, ncol = nw * 48;
    float acc[2][6][4] = {};
    int lrow = lane & 15, lk = (lane >> 4) << 3;
    int brow = (lane & 7) + ((lane >> 4) & 1) * 8;
    int bk = ((lane >> 3) & 1) << 3;
#pragma unroll
    for (int kf = 0; kf < 8; kf++) {
        int k0 = kf << 4;
        uint32_t ah[2][4], al[2][4];
#pragma unroll
        for (int mi = 0; mi < 2; mi++) {
            uint32_t ad = sb + (uint32_t)(((arow + mi * 16 + lrow) * 136 + k0 + lk) * 2);
            LDSM4(ah[mi], ad + IP_AH * 2);
            LDSM4(al[mi], ad + IP_AL * 2);
        }
        uint32_t bh[3][4], bl[3][4];
#pragma unroll
        for (int ng = 0; ng < 3; ng++) {
            uint32_t ad = sb + (uint32_t)(((ncol + ng * 16 + brow) * 136 + k0 + bk) * 2);
            LDSM4(bh[ng], ad + IP_BH * 2);
            LDSM4(bl[ng], ad + IP_BL * 2);
        }
#pragma unroll
        for (int mi = 0; mi < 2; mi++)
#pragma unroll
            for (int nf = 0; nf < 6; nf++) {
                uint32_t* BH = &bh[nf >> 1][(nf & 1) * 2];
                uint32_t* BL = &bl[nf >> 1][(nf & 1) * 2];
                MMA16816(acc[mi][nf], ah[mi], BH[0], BH[1]);
                MMA16816(acc[mi][nf], ah[mi], BL[0], BL[1]);
                MMA16816(acc[mi][nf], al[mi], BH[0], BH[1]);
            }
    }
    int g = lane >> 2, tg = lane & 3;
#pragma unroll
    for (int mi = 0; mi < 2; mi++) {
        int r = rowBase + arow + mi * 16 + g;
#pragma unroll
        for (int nf = 0; nf < 6; nf++) {
            int c = colBase + ncol + nf * 8 + tg * 2;
            if (c < DPROJ) {
                *(float2*)&g_zx[(size_t)r * DPROJ + c] =
                    make_float2(acc[mi][nf][0], acc[mi][nf][1]);
                *(float2*)&g_zx[(size_t)(r + 8) * DPROJ + c] =
                    make_float2(acc[mi][nf][2], acc[mi][nf][3]);
            }
        }
    }
}

// ---------------- K2: conv(K=4)+SiLU; exact fp32 dt -------------------------
__global__ void k_conv(const float* __restrict__ cw, const float* __restrict__ cb,
                       const float* __restrict__ dtb, const float* __restrict__ Wi) {
    int r = blockIdx.x;
    int t = r & (LSEQ - 1);
    int tid = threadIdx.x;
#pragma unroll
    for (int cc = 0; cc < 3; cc++) {
        int c = tid + cc * 128;
        float acc = cb[c];
#pragma unroll
        for (int k = 0; k < 4; k++) {
            int tt = t - 3 + k;
            if (tt >= 0)
                acc += g_zx[(size_t)(r - 3 + k) * DPROJ + 256 + c] * cw[c * 4 + k];
        }
        g_xc[(size_t)r * CONVD + c] = acc / (1.f + __expf(-acc));
    }
    // exact dt: fp32 dot of xn row with W rows 640..647
    {
        int hh = tid >> 4, sl = tid & 15;
        const float4* xr = (const float4*)(g_xn + (size_t)r * DMODEL);
        const float4* wr = (const float4*)(Wi + (size_t)(640 + hh) * DMODEL);
        float4 x0 = xr[sl * 2], x1 = xr[sl * 2 + 1];
        float4 w0 = wr[sl * 2], w1 = wr[sl * 2 + 1];
        float s = x0.x * w0.x + x0.y * w0.y + x0.z * w0.z + x0.w * w0.w
                + x1.x * w1.x + x1.y * w1.y + x1.z * w1.z + x1.w * w1.w;
#pragma unroll
        for (int o = 8; o; o >>= 1) s += __shfl_xor_sync(0xffffffffu, s, o);
        if (sl == 0) {
            float v = s + dtb[hh];
            g_dtb[(size_t)r * NH + hh] = (v > 20.f) ? v : log1pf(__expf(v));
        }
    }
}

// ---------------- SSD pass A ------------------------------------------------
__global__ void __launch_bounds__(128) k_ssd_a(const float* __restrict__ A_log) {
    __shared__ __align__(16) float Bs[64 * 68];
    __shared__ __align__(16) float Xs[64 * 36];
    __shared__ float sdt[64], sS[64], ssc[64];
    int tid = threadIdx.x;
    int cid = blockIdx.x;
    int bh = cid >> 6, c = cid & 63;
    int b = bh >> 3, h = bh & 7;
    int r0 = b * LSEQ + c * QC;
    float A = -__expf(A_log[h]);
    if (tid < 64) sdt[tid] = g_dtb[(size_t)(r0 + tid) * NH + h];
    for (int i = tid; i < 1024; i += 128) {
        int s = i >> 4, q = i & 15;
        *(float4*)&Bs[s * 68 + q * 4] =
            *(const float4*)&g_xc[(size_t)(r0 + s) * CONVD + 256 + q * 4];
    }
    __syncthreads();
    if (tid < 64) {
        float v = sdt[tid] * A;
#pragma unroll
        for (int o = 1; o < 32; o <<= 1) {
            float u = __shfl_up_sync(0xffffffffu, v, o);
            if ((tid & 31) >= o) v += u;
        }
        sS[tid] = v;
    }
    __syncthreads();
    if (tid >= 32 && tid < 64) sS[tid] += sS[31];
    __syncthreads();
    float T = sS[63];
    if (tid < 64) {
        float sv = sS[tid];
        g_S[(size_t)cid * QC + tid] = sv;
        ssc[tid] = __expf(T - sv) * sdt[tid];
    }
    if (tid == 0) g_T[cid] = T;
    __syncthreads();
    for (int i = tid; i < 512; i += 128) {
        int s = i >> 3, q = i & 7;
        float4 v = *(const float4*)&g_xc[(size_t)(r0 + s) * CONVD + h * HD + q * 4];
        float sc = ssc[s];
        v.x *= sc; v.y *= sc; v.z *= sc; v.w *= sc;
        *(float4*)&Xs[s * 36 + q * 4] = v;
    }
    __syncthreads();
    int ty = tid >> 4, tx = tid & 15;
    unsigned long long acc[4][2] = {};
#pragma unroll 4
    for (int s = 0; s < 64; s++) {
        unsigned long long b0 = *(const unsigned long long*)&Bs[s * 68 + 2 * tx];
        unsigned long long b1 = *(const unsigned long long*)&Bs[s * 68 + 2 * tx + 32];
#pragma unroll
        for (int i = 0; i < 4; i++) {
            unsigned long long xa = pack2(Xs[s * 36 + ty + 8 * i]);
            acc[i][0] = fma2(xa, b0, acc[i][0]);
            acc[i][1] = fma2(xa, b1, acc[i][1]);
        }
    }
    size_t ub = (size_t)cid * 2048;
#pragma unroll
    for (int i = 0; i < 4; i++) {
        int p = ty + 8 * i;
        *(unsigned long long*)&g_U[ub + p * 64 + 2 * tx]      = acc[i][0];
        *(unsigned long long*)&g_U[ub + p * 64 + 2 * tx + 32] = acc[i][1];
    }
}

// ---------------- SSD pass B ------------------------------------------------
__global__ void k_ssd_b() {
    int bh   = blockIdx.x >> 1;
    int half = blockIdx.x & 1;
    int tid  = threadIdx.x;  // 256
    size_t base = (size_t)bh * NCHK;
    size_t o0 = base * 2048 + half * 1024 + tid * 4;
    float4 h0 = make_float4(0.f, 0.f, 0.f, 0.f);
    float4 u0 = *(const float4*)&g_U[o0];
    for (int c = 0; c < NCHK; c++) {
        size_t off = (size_t)c * 2048;
        *(float4*)&g_hs[o0 + off] = h0;
        float e = __expf(g_T[base + c]);
        float4 n0 = make_float4(0.f, 0.f, 0.f, 0.f);
        if (c + 1 < NCHK) n0 = *(const float4*)&g_U[o0 + off + 2048];
        h0.x = e * h0.x + u0.x; h0.y = e * h0.y + u0.y;
        h0.z = e * h0.z + u0.z; h0.w = e * h0.w + u0.w;
        u0 = n0;
    }
}

// ---------------- SSD pass C --------------------------------------------------
__global__ void __launch_bounds__(256, 2) k_ssd_c(const float* __restrict__ Dp) {
    extern __shared__ float sm[];
    float* Cs  = sm;             // [64][68]
    float* Bm  = sm + 4352;      // [64][68]
    float* XT  = sm + 8704;      // [32][68]
    float* hsm = sm + 10880;     // [32][68]
    float* Ssm = sm + 13056;
    float* dts = sm + 13120;
    int tid = threadIdx.x;
    int cid = blockIdx.x;
    int bh = cid >> 6, c = cid & 63;
    int b = bh >> 3, h = bh & 7;
    int r0 = b * LSEQ + c * QC;
    float Dh = Dp[h];

    for (int i = tid; i < 1024; i += 256) {
        int s = i >> 4, q = i & 15;
        *(float4*)&Cs[s * 68 + q * 4] =
            *(const float4*)&g_xc[(size_t)(r0 + s) * CONVD + 320 + q * 4];
        *(float4*)&Bm[s * 68 + q * 4] =
            *(const float4*)&g_xc[(size_t)(r0 + s) * CONVD + 256 + q * 4];
    }
    for (int i = tid; i < 512; i += 256) {
        int s = i >> 3, q = i & 7;
        float4 v = *(const float4*)&g_xc[(size_t)(r0 + s) * CONVD + h * HD + q * 4];
        XT[(q * 4 + 0) * 68 + s] = v.x;
        XT[(q * 4 + 1) * 68 + s] = v.y;
        XT[(q * 4 + 2) * 68 + s] = v.z;
        XT[(q * 4 + 3) * 68 + s] = v.w;
    }
    for (int i = tid; i < 512; i += 256) {
        int p = i >> 4, q = i & 15;
        *(float4*)&hsm[p * 68 + q * 4] =
            *(const float4*)&g_hs[(size_t)cid * 2048 + i * 4];
    }
    if (tid < 64) {
        Ssm[tid] = g_S[(size_t)cid * QC + tid];
        dts[tid] = g_dtb[(size_t)(r0 + tid) * NH + h];
    }
    __syncthreads();

    int ty = tid >> 4, tx = tid & 15;
    unsigned long long g2[4][4] = {};
#pragma unroll 4
    for (int kp = 0; kp < 32; kp++) {
        unsigned long long a[4], bb[4];
#pragma unroll
        for (int i = 0; i < 4; i++)
            a[i] = *(const unsigned long long*)&Cs[(ty + 16 * i) * 68 + 2 * kp];
#pragma unroll
        for (int j = 0; j < 4; j++)
            bb[j] = *(const unsigned long long*)&Bm[(tx + 16 * j) * 68 + 2 * kp];
#pragma unroll
        for (int i = 0; i < 4; i++)
#pragma unroll
            for (int j = 0; j < 4; j++) g2[i][j] = fma2(a[i], bb[j], g2[i][j]);
    }
    float Gv[4][4];
#pragma unroll
    for (int i = 0; i < 4; i++)
#pragma unroll
        for (int j = 0; j < 4; j++) Gv[i][j] = lohi_sum(g2[i][j]);
    __syncthreads();

#pragma unroll
    for (int i = 0; i < 4; i++) {
        int t = ty + 16 * i;
        float St = Ssm[t];
#pragma unroll
        for (int j = 0; j < 4; j++) {
            int s = tx + 16 * j;
            float m = 0.f;
            if (s <= t) m = Gv[i][j] * __expf(St - Ssm[s]) * dts[s];
            Bm[t * 68 + s] = m;
        }
    }
    __syncthreads();

    unsigned long long yi[4][2] = {}, yo[4][2] = {};
#pragma unroll 2
    for (int sp = 0; sp < 32; sp++) {
        unsigned long long a[4], ca[4];
#pragma unroll
        for (int i = 0; i < 4; i++)
            a[i] = *(const unsigned long long*)&Bm[(ty + 16 * i) * 68 + 2 * sp];
        unsigned long long x0 = *(const unsigned long long*)&XT[tx * 68 + 2 * sp];
        unsigned long long x1 = *(const unsigned long long*)&XT[(tx + 16) * 68 + 2 * sp];
#pragma unroll
        for (int i = 0; i < 4; i++) {
            yi[i][0] = fma2(a[i], x0, yi[i][0]);
            yi[i][1] = fma2(a[i], x1, yi[i][1]);
        }
#pragma unroll
        for (int i = 0; i < 4; i++)
            ca[i] = *(const unsigned long long*)&Cs[(ty + 16 * i) * 68 + 2 * sp];
        unsigned long long h0 = *(const unsigned long long*)&hsm[tx * 68 + 2 * sp];
        unsigned long long h1 = *(const unsigned long long*)&hsm[(tx + 16) * 68 + 2 * sp];
#pragma unroll
        for (int i = 0; i < 4; i++) {
            yo[i][0] = fma2(ca[i], h0, yo[i][0]);
            yo[i][1] = fma2(ca[i], h1, yo[i][1]);
        }
    }
#pragma unroll
    for (int i = 0; i < 4; i++) {
        int t = ty + 16 * i;
        float et = __expf(Ssm[t]);
#pragma unroll
        for (int l = 0; l < 2; l++) {
            int p = tx + 16 * l;
            float yv = lohi_sum(yi[i][l]) + et * lohi_sum(yo[i][l])
                     + Dh * XT[p * 68 + t];
            g_y[(size_t)(r0 + t) * DINNER + h * HD + p] = yv;
        }
    }
}

// ---------------- K4a: gating + gated RMSNorm -> bf16 splits ----------------
__global__ void k_gate(const float* __restrict__ gw) {
    int r = blockIdx.x;
    int i = threadIdx.x;
    float yv = g_y[(size_t)r * DINNER + i];
    float zv = g_zx[(size_t)r * DPROJ + i];
    float gv = yv * (zv / (1.f + __expf(-zv)));
    float ss = gv * gv;
#pragma unroll
    for (int o = 16; o; o >>= 1) ss += __shfl_xor_sync(0xffffffffu, ss, o);
    __shared__ float red[8];
    if ((i & 31) == 0) red[i >> 5] = ss;
    __syncthreads();
    float tot = red[0] + red[1] + red[2] + red[3] + red[4] + red[5] + red[6] + red[7];
    float sc = rsqrtf(tot * (1.f / DINNER) + 1e-5f);
    float v = gv * sc * gw[i];
    __nv_bfloat16 h, l;
    split_bf16(v, h, l);
    g_gh[(size_t)r * DINNER + i] = h;
    g_gl[(size_t)r * DINNER + i] = l;
}

// ---------------- K4b: out_proj HMMA bf16x3 + residual, tile 128x128 K=256 --
#define OP_AH 0
#define OP_AL 17408
#define OP_BH 34816
#define OP_BL 52224
#define OP_TOT 69632   // elements -> 139264 bytes
__global__ void __launch_bounds__(256, 1) k_outproj_mma(const float* __restrict__ x,
                                                        float* __restrict__ out) {
    extern __shared__ __align__(16) __nv_bfloat16 smb[];
    int tid = threadIdx.x, wid = tid >> 5, lane = tid & 31;
    int rowBase = blockIdx.x * 128;
    uint32_t sb = smem_u32(smb);
    int mw = wid & 3, nw = wid >> 2;
    int arow = mw * 32, ncol = nw * 64;
    float acc[2][8][4] = {};
    int lrow = lane & 15, lk = (lane >> 4) << 3;
    int brow = (lane & 7) + ((lane >> 4) & 1) * 8;
    int bk = ((lane >> 3) & 1) << 3;

    for (int kc = 0; kc < 2; kc++) {
        if (kc) __syncthreads();
        for (int i = tid; i < 2048; i += 256) {
            int r = i >> 4, c = (i & 15) << 3;
            size_t ao = (size_t)(rowBase + r) * DINNER + kc * 128 + c;
            *(uint4*)&smb[OP_AH + r * 136 + c] = *(const uint4*)(g_gh + ao);
            *(uint4*)&smb[OP_AL + r * 136 + c] = *(const uint4*)(g_gl + ao);
            size_t bo = (size_t)r * DINNER + kc * 128 + c;
            *(uint4*)&smb[OP_BH + r * 136 + c] = *(const uint4*)(g_woh + bo);
            *(uint4*)&smb[OP_BL + r * 136 + c] = *(const uint4*)(g_wol + bo);
        }
        __syncthreads();
#pragma unroll
        for (int kf = 0; kf < 8; kf++) {
            int k0 = kf << 4;
            uint32_t ah[2][4], al[2][4];
#pragma unroll
            for (int mi = 0; mi < 2; mi++) {
                uint32_t ad = sb + (uint32_t)(((arow + mi * 16 + lrow) * 136 + k0 + lk) * 2);
                LDSM4(ah[mi], ad + OP_AH * 2);
                LDSM4(al[mi], ad + OP_AL * 2);
            }
            uint32_t bh[4][4], bl[4][4];
#pragma unroll
            for (int ng = 0; ng < 4; ng++) {
                uint32_t ad = sb + (uint32_t)(((ncol + ng * 16 + brow) * 136 + k0 + bk) * 2);
                LDSM4(bh[ng], ad + OP_BH * 2);
                LDSM4(bl[ng], ad + OP_BL * 2);
            }
#pragma unroll
            for (int mi = 0; mi < 2; mi++)
#pragma unroll
                for (int nf = 0; nf < 8; nf++) {
                    uint32_t* BH = &bh[nf >> 1][(nf & 1) * 2];
                    uint32_t* BL = &bl[nf >> 1][(nf & 1) * 2];
                    MMA16816(acc[mi][nf], ah[mi], BH[0], BH[1]);
                    MMA16816(acc[mi][nf], ah[mi], BL[0], BL[1]);
                    MMA16816(acc[mi][nf], al[mi], BH[0], BH[1]);
                }
        }
    }
    int g = lane >> 2, tg = lane & 3;
#pragma unroll
    for (int mi = 0; mi < 2; mi++) {
        int r = rowBase + arow + mi * 16 + g;
#pragma unroll
        for (int nf = 0; nf < 8; nf++) {
            int c = ncol + nf * 8 + tg * 2;
            float2 x0 = *(const float2*)&x[(size_t)r * DMODEL + c];
            float2 x1 = *(const float2*)&x[(size_t)(r + 8) * DMODEL + c];
            *(float2*)&out[(size_t)r * DMODEL + c] =
                make_float2(acc[mi][nf][0] + x0.x, acc[mi][nf][1] + x0.y);
            *(float2*)&out[(size_t)(r + 8) * DMODEL + c] =
                make_float2(acc[mi][nf][2] + x1.x, acc[mi][nf][3] + x1.y);
        }
    }
}

extern "C" void kernel_launch(void* const* d_in, const int* in_sizes, int n_in,
                              void* d_out, int out_size) {
    const float* x          = (const float*)d_in[0];
    const float* norm_w     = (const float*)d_in[1];
    const float* in_proj_w  = (const float*)d_in[2];
    const float* conv_w     = (const float*)d_in[3];
    const float* conv_b     = (const float*)d_in[4];
    const float* dt_bias    = (const float*)d_in[5];
    const float* A_log      = (const float*)d_in[6];
    const float* D          = (const float*)d_in[7];
    const float* gnorm_w    = (const float*)d_in[8];
    const float* out_proj_w = (const float*)d_in[9];
    float* out = (float*)d_out;

    const int in_smem   = IP_TOT * 2;   // 121856 B
    const int out_smem  = OP_TOT * 2;   // 139264 B
    const int ssdc_smem = 13184 * 4;
    cudaFuncSetAttribute(k_inproj_mma,  cudaFuncAttributeMaxDynamicSharedMemorySize, in_smem);
    cudaFuncSetAttribute(k_outproj_mma, cudaFuncAttributeMaxDynamicSharedMemorySize, out_smem);
    cudaFuncSetAttribute(k_ssd_c,       cudaFuncAttributeMaxDynamicSharedMemorySize, ssdc_smem);

    k_wsplit<<<113, 256>>>(in_proj_w, out_proj_w);
    k_rmsnorm<<<RTOT / 8, 256>>>(x, norm_w);
    k_inproj_mma<<<dim3(RTOT / 128, 7), 256, in_smem>>>();
    k_conv<<<RTOT, 128>>>(conv_w, conv_b, dt_bias, in_proj_w);
    k_ssd_a<<<NCID, 128>>>(A_log);
    k_ssd_b<<<NBATCH * NH * 2, 256>>>();
    k_ssd_c<<<NCID, 256, ssdc_smem>>>(D);
    k_gate<<<RTOT, 256>>>(gnorm_w);
    k_outproj_mma<<<RTOT / 128, 256, out_smem>>>(x, out);
}

// round 6
// speedup vs baseline: 2.3492x; 1.1875x over previous
#include <cuda_runtime.h>
#include <cuda_bf16.h>
#include <cstdint>

#define RTOT   32768
#define LSEQ   4096
#define NBATCH 8
#define DMODEL 128
#define DPROJ  648
#define DINNER 256
#define CONVD  384
#define NH     8
#define HD     32
#define QC     64
#define NCHK   (LSEQ/QC)
#define NCID   (NBATCH*NH*NCHK)

// ---------------- scratch (device globals) ----------------------------------
__device__ __align__(16) float g_xn [RTOT * DMODEL];
__device__ __align__(16) float g_zx [(size_t)RTOT * DPROJ];
__device__ __align__(16) float g_xc [RTOT * CONVD];
__device__ __align__(16) float g_dtb[RTOT * NH];
__device__ __align__(16) float g_y  [RTOT * DINNER];
__device__ __align__(16) float g_U  [(size_t)NCID * 2048];
__device__ __align__(16) float g_hs [(size_t)NCID * 2048];
__device__ __align__(16) float g_S  [(size_t)NCID * QC];
__device__ __align__(16) float g_T  [NCID];
__device__ __align__(16) __nv_bfloat16 g_ah [RTOT * DMODEL];
__device__ __align__(16) __nv_bfloat16 g_al [RTOT * DMODEL];
__device__ __align__(16) __nv_bfloat16 g_wih[672 * DMODEL];
__device__ __align__(16) __nv_bfloat16 g_wil[672 * DMODEL];
__device__ __align__(16) __nv_bfloat16 g_gh [RTOT * DINNER];
__device__ __align__(16) __nv_bfloat16 g_gl [RTOT * DINNER];
__device__ __align__(16) __nv_bfloat16 g_woh[DMODEL * DINNER];
__device__ __align__(16) __nv_bfloat16 g_wol[DMODEL * DINNER];
// -----------------------------------------------------------------------------

// ---- fp32x2 helpers ----
static __device__ __forceinline__ unsigned long long fma2(unsigned long long a,
                                                          unsigned long long b,
                                                          unsigned long long c) {
    unsigned long long d;
    asm("fma.rn.f32x2 %0, %1, %2, %3;" : "=l"(d) : "l"(a), "l"(b), "l"(c));
    return d;
}
static __device__ __forceinline__ unsigned long long pack2(float v) {
    unsigned long long r;
    asm("mov.b64 %0, {%1, %1};" : "=l"(r) : "f"(v));
    return r;
}

// ---- warp MMA helpers ----
static __device__ __forceinline__ uint32_t smem_u32(const void* p) {
    uint32_t a;
    asm("{ .reg .u64 t; cvta.to.shared.u64 t, %1; cvt.u32.u64 %0, t; }"
        : "=r"(a) : "l"(p));
    return a;
}
#define LDSM4(r, addr) \
    asm volatile("ldmatrix.sync.aligned.m8n8.x4.shared.b16 {%0,%1,%2,%3}, [%4];" \
        : "=r"((r)[0]), "=r"((r)[1]), "=r"((r)[2]), "=r"((r)[3]) : "r"(addr))
#define MMA16816(d, a, b0, b1) \
    asm volatile("mma.sync.aligned.m16n8k16.row.col.f32.bf16.bf16.f32 " \
        "{%0,%1,%2,%3}, {%4,%5,%6,%7}, {%8,%9}, {%0,%1,%2,%3};" \
        : "+f"((d)[0]), "+f"((d)[1]), "+f"((d)[2]), "+f"((d)[3]) \
        : "r"((a)[0]), "r"((a)[1]), "r"((a)[2]), "r"((a)[3]), "r"(b0), "r"(b1))

static __device__ __forceinline__ void split_bf16(float v, __nv_bfloat16& h,
                                                  __nv_bfloat16& l) {
    h = __float2bfloat16(v);
    l = __float2bfloat16(v - __bfloat162float(h));
}
static __device__ __forceinline__ void split4(float4 v, __nv_bfloat16* h,
                                              __nv_bfloat16* l) {
    split_bf16(v.x, h[0], l[0]); split_bf16(v.y, h[1], l[1]);
    split_bf16(v.z, h[2], l[2]); split_bf16(v.w, h[3], l[3]);
}

// ---------------- K_w: one-shot weight split -------------------------------
__global__ void k_wsplit(const float* __restrict__ Wi, const float* __restrict__ Wo) {
    int idx = blockIdx.x * 256 + threadIdx.x;
    const int NWI = DPROJ * DMODEL / 4;
    const int NWO = DMODEL * DINNER / 4;
    if (idx < NWI) {
        float4 v = ((const float4*)Wi)[idx];
        __nv_bfloat16 h[4], l[4];
        split4(v, h, l);
        ((uint2*)g_wih)[idx] = *(uint2*)h;
        ((uint2*)g_wil)[idx] = *(uint2*)l;
    } else if (idx < NWI + NWO) {
        int j = idx - NWI;
        float4 v = ((const float4*)Wo)[j];
        __nv_bfloat16 h[4], l[4];
        split4(v, h, l);
        ((uint2*)g_woh)[j] = *(uint2*)h;
        ((uint2*)g_wol)[j] = *(uint2*)l;
    }
}

// ---------------- K0: RMSNorm -> fp32 + bf16 hi/lo splits -------------------
__global__ void k_rmsnorm(const float* __restrict__ x, const float* __restrict__ w) {
    int row  = blockIdx.x * 8 + (threadIdx.x >> 5);
    int lane = threadIdx.x & 31;
    float4 v = ((const float4*)(x + (size_t)row * DMODEL))[lane];
    float ss = v.x * v.x + v.y * v.y + v.z * v.z + v.w * v.w;
#pragma unroll
    for (int o = 16; o; o >>= 1) ss += __shfl_xor_sync(0xffffffffu, ss, o);
    float sc = rsqrtf(ss * (1.f / DMODEL) + 1e-5f);
    float4 wv = ((const float4*)w)[lane];
    float4 o4;
    o4.x = v.x * sc * wv.x; o4.y = v.y * sc * wv.y;
    o4.z = v.z * sc * wv.z; o4.w = v.w * sc * wv.w;
    ((float4*)(g_xn + (size_t)row * DMODEL))[lane] = o4;
    __nv_bfloat16 h[4], l[4];
    split4(o4, h, l);
    ((uint2*)(g_ah + (size_t)row * DMODEL))[lane] = *(uint2*)h;
    ((uint2*)(g_al + (size_t)row * DMODEL))[lane] = *(uint2*)l;
}

// ---------------- K1: in_proj GEMM via HMMA bf16x3, tile 128x96, K=128 ------
#define IP_AH 0
#define IP_AL 17408
#define IP_BH 34816
#define IP_BL 47872
#define IP_TOT 60928
__global__ void __launch_bounds__(256, 1) k_inproj_mma() {
    extern __shared__ __align__(16) __nv_bfloat16 smb[];
    int tid = threadIdx.x, wid = tid >> 5, lane = tid & 31;
    int rowBase = blockIdx.x * 128;
    int colBase = blockIdx.y * 96;

    for (int i = tid; i < 2048; i += 256) {
        int r = i >> 4, c = (i & 15) << 3;
        *(uint4*)&smb[IP_AH + r * 136 + c] =
            *(const uint4*)(g_ah + (size_t)(rowBase + r) * DMODEL + c);
        *(uint4*)&smb[IP_AL + r * 136 + c] =
            *(const uint4*)(g_al + (size_t)(rowBase + r) * DMODEL + c);
    }
    for (int i = tid; i < 1536; i += 256) {
        int r = i >> 4, c = (i & 15) << 3;
        *(uint4*)&smb[IP_BH + r * 136 + c] =
            *(const uint4*)(g_wih + (size_t)(colBase + r) * DMODEL + c);
        *(uint4*)&smb[IP_BL + r * 136 + c] =
            *(const uint4*)(g_wil + (size_t)(colBase + r) * DMODEL + c);
    }
    __syncthreads();

    uint32_t sb = smem_u32(smb);
    int mw = wid & 3, nw = wid >> 2;
    int arow = mw * 32, ncol = nw * 48;
    float acc[2][6][4] = {};
    int lrow = lane & 15, lk = (lane >> 4) << 3;
    int brow = (lane & 7) + ((lane >> 4) & 1) * 8;
    int bk = ((lane >> 3) & 1) << 3;
#pragma unroll
    for (int kf = 0; kf < 8; kf++) {
        int k0 = kf << 4;
        uint32_t ah[2][4], al[2][4];
#pragma unroll
        for (int mi = 0; mi < 2; mi++) {
            uint32_t ad = sb + (uint32_t)(((arow + mi * 16 + lrow) * 136 + k0 + lk) * 2);
            LDSM4(ah[mi], ad + IP_AH * 2);
            LDSM4(al[mi], ad + IP_AL * 2);
        }
        uint32_t bh[3][4], bl[3][4];
#pragma unroll
        for (int ng = 0; ng < 3; ng++) {
            uint32_t ad = sb + (uint32_t)(((ncol + ng * 16 + brow) * 136 + k0 + bk) * 2);
            LDSM4(bh[ng], ad + IP_BH * 2);
            LDSM4(bl[ng], ad + IP_BL * 2);
        }
#pragma unroll
        for (int mi = 0; mi < 2; mi++)
#pragma unroll
            for (int nf = 0; nf < 6; nf++) {
                uint32_t* BH = &bh[nf >> 1][(nf & 1) * 2];
                uint32_t* BL = &bl[nf >> 1][(nf & 1) * 2];
                MMA16816(acc[mi][nf], ah[mi], BH[0], BH[1]);
                MMA16816(acc[mi][nf], ah[mi], BL[0], BL[1]);
                MMA16816(acc[mi][nf], al[mi], BH[0], BH[1]);
            }
    }
    int g = lane >> 2, tg = lane & 3;
#pragma unroll
    for (int mi = 0; mi < 2; mi++) {
        int r = rowBase + arow + mi * 16 + g;
#pragma unroll
        for (int nf = 0; nf < 6; nf++) {
            int c = colBase + ncol + nf * 8 + tg * 2;
            if (c < DPROJ) {
                *(float2*)&g_zx[(size_t)r * DPROJ + c] =
                    make_float2(acc[mi][nf][0], acc[mi][nf][1]);
                *(float2*)&g_zx[(size_t)(r + 8) * DPROJ + c] =
                    make_float2(acc[mi][nf][2], acc[mi][nf][3]);
            }
        }
    }
}

// ---------------- K_dt: exact fp32 dt GEMV + softplus ----------------------
__global__ void k_dt(const float* __restrict__ Wi, const float* __restrict__ dtb) {
    int r  = blockIdx.x * 2 + (threadIdx.x >> 7);
    int t  = threadIdx.x & 127;
    int hh = t >> 4, sl = t & 15;
    const float4* xr = (const float4*)(g_xn + (size_t)r * DMODEL);
    const float4* wr = (const float4*)(Wi + (size_t)(640 + hh) * DMODEL);
    float4 x0 = xr[sl * 2], x1 = xr[sl * 2 + 1];
    float4 w0 = wr[sl * 2], w1 = wr[sl * 2 + 1];
    float s = x0.x * w0.x + x0.y * w0.y + x0.z * w0.z + x0.w * w0.w
            + x1.x * w1.x + x1.y * w1.y + x1.z * w1.z + x1.w * w1.w;
#pragma unroll
    for (int o = 8; o; o >>= 1) s += __shfl_xor_sync(0xffffffffu, s, o);
    if (sl == 0) {
        float v = s + dtb[hh];
        g_dtb[(size_t)r * NH + hh] = (v > 20.f) ? v : log1pf(__expf(v));
    }
}

// ---------------- K2: conv(K=4)+SiLU, sliding-window ------------------------
__global__ void k_conv2(const float* __restrict__ cw, const float* __restrict__ cb) {
    int c  = blockIdx.y * 128 + threadIdx.x;
    int r0 = blockIdx.x * 32;
    bool hist = (r0 & (LSEQ - 1)) != 0;
    float w0 = cw[c * 4 + 0], w1 = cw[c * 4 + 1];
    float w2 = cw[c * 4 + 2], w3 = cw[c * 4 + 3];
    float bias = cb[c];
    const float* src = g_zx + 256 + c;
    float* dst = g_xc + c;
    float x0 = hist ? src[(size_t)(r0 - 3) * DPROJ] : 0.f;
    float x1 = hist ? src[(size_t)(r0 - 2) * DPROJ] : 0.f;
    float x2 = hist ? src[(size_t)(r0 - 1) * DPROJ] : 0.f;
#pragma unroll 8
    for (int s = 0; s < 32; s++) {
        int r = r0 + s;
        float x3 = src[(size_t)r * DPROJ];
        float acc = bias + w0 * x0 + w1 * x1 + w2 * x2 + w3 * x3;
        dst[(size_t)r * CONVD] = acc / (1.f + __expf(-acc));
        x0 = x1; x1 = x2; x2 = x3;
    }
}

// ---------------- SSD pass A ------------------------------------------------
__global__ void __launch_bounds__(128) k_ssd_a(const float* __restrict__ A_log) {
    __shared__ __align__(16) float Bs[64 * 68];
    __shared__ __align__(16) float Xs[64 * 36];
    __shared__ float sdt[64], sS[64], ssc[64];
    int tid = threadIdx.x;
    int cid = blockIdx.x;
    int bh = cid >> 6, c = cid & 63;
    int b = bh >> 3, h = bh & 7;
    int r0 = b * LSEQ + c * QC;
    float A = -__expf(A_log[h]);
    if (tid < 64) sdt[tid] = g_dtb[(size_t)(r0 + tid) * NH + h];
    for (int i = tid; i < 1024; i += 128) {
        int s = i >> 4, q = i & 15;
        *(float4*)&Bs[s * 68 + q * 4] =
            *(const float4*)&g_xc[(size_t)(r0 + s) * CONVD + 256 + q * 4];
    }
    __syncthreads();
    if (tid < 64) {
        float v = sdt[tid] * A;
#pragma unroll
        for (int o = 1; o < 32; o <<= 1) {
            float u = __shfl_up_sync(0xffffffffu, v, o);
            if ((tid & 31) >= o) v += u;
        }
        sS[tid] = v;
    }
    __syncthreads();
    if (tid >= 32 && tid < 64) sS[tid] += sS[31];
    __syncthreads();
    float T = sS[63];
    if (tid < 64) {
        float sv = sS[tid];
        g_S[(size_t)cid * QC + tid] = sv;
        ssc[tid] = __expf(T - sv) * sdt[tid];
    }
    if (tid == 0) g_T[cid] = T;
    __syncthreads();
    for (int i = tid; i < 512; i += 128) {
        int s = i >> 3, q = i & 7;
        float4 v = *(const float4*)&g_xc[(size_t)(r0 + s) * CONVD + h * HD + q * 4];
        float sc = ssc[s];
        v.x *= sc; v.y *= sc; v.z *= sc; v.w *= sc;
        *(float4*)&Xs[s * 36 + q * 4] = v;
    }
    __syncthreads();
    int ty = tid >> 4, tx = tid & 15;
    unsigned long long acc[4][2] = {};
#pragma unroll 4
    for (int s = 0; s < 64; s++) {
        unsigned long long b0 = *(const unsigned long long*)&Bs[s * 68 + 2 * tx];
        unsigned long long b1 = *(const unsigned long long*)&Bs[s * 68 + 2 * tx + 32];
#pragma unroll
        for (int i = 0; i < 4; i++) {
            unsigned long long xa = pack2(Xs[s * 36 + ty + 8 * i]);
            acc[i][0] = fma2(xa, b0, acc[i][0]);
            acc[i][1] = fma2(xa, b1, acc[i][1]);
        }
    }
    size_t ub = (size_t)cid * 2048;
#pragma unroll
    for (int i = 0; i < 4; i++) {
        int p = ty + 8 * i;
        *(unsigned long long*)&g_U[ub + p * 64 + 2 * tx]      = acc[i][0];
        *(unsigned long long*)&g_U[ub + p * 64 + 2 * tx + 32] = acc[i][1];
    }
}

// ---------------- SSD pass B ------------------------------------------------
__global__ void k_ssd_b() {
    __shared__ float sT[NCHK];
    int bh   = blockIdx.x >> 1;
    int half = blockIdx.x & 1;
    int tid  = threadIdx.x;  // 256
    size_t base = (size_t)bh * NCHK;
    if (tid < NCHK) sT[tid] = __expf(g_T[base + tid]);
    __syncthreads();
    size_t o0 = base * 2048 + half * 1024 + tid * 4;
    float4 h0 = make_float4(0.f, 0.f, 0.f, 0.f);
    float4 u0 = *(const float4*)&g_U[o0];
    for (int c = 0; c < NCHK; c++) {
        size_t off = (size_t)c * 2048;
        *(float4*)&g_hs[o0 + off] = h0;
        float e = sT[c];
        float4 n0 = make_float4(0.f, 0.f, 0.f, 0.f);
        if (c + 1 < NCHK) n0 = *(const float4*)&g_U[o0 + off + 2048];
        h0.x = e * h0.x + u0.x; h0.y = e * h0.y + u0.y;
        h0.z = e * h0.z + u0.z; h0.w = e * h0.w + u0.w;
        u0 = n0;
    }
}

// ---------------- SSD pass C via HMMA bf16x3 --------------------------------
// pitch 72 bf16 elements (144B) -> ldmatrix conflict-free, 16B-aligned rows
#define SC_P  72
#define SC_CH 0
#define SC_CL 4608
#define SC_BH 9216     /* later reused as M hi */
#define SC_BL 13824    /* later reused as M lo */
#define SC_XH 18432
#define SC_XL 20736
#define SC_HH 23040
#define SC_HL 25344
#define SC_END 27648   /* bf16 elements; floats after */
__global__ void __launch_bounds__(256, 2) k_ssd_c_mma(const float* __restrict__ Dp) {
    extern __shared__ __align__(16) __nv_bfloat16 smb[];
    float* Ssm = (float*)(smb + SC_END);
    float* dts = Ssm + 64;
    int tid = threadIdx.x, wid = tid >> 5, lane = tid & 31;
    int cid = blockIdx.x;
    int bh = cid >> 6, c = cid & 63;
    int b = bh >> 3, h = bh & 7;
    int r0 = b * LSEQ + c * QC;
    float Dh = Dp[h];

    // stage C, B (64x64) split to hi/lo
    for (int i = tid; i < 1024; i += 256) {
        int s = i >> 4, q = (i & 15) * 4;
        float4 cv = *(const float4*)&g_xc[(size_t)(r0 + s) * CONVD + 320 + q];
        float4 bv = *(const float4*)&g_xc[(size_t)(r0 + s) * CONVD + 256 + q];
        __nv_bfloat16 h4[4], l4[4];
        split4(cv, h4, l4);
        *(uint2*)&smb[SC_CH + s * SC_P + q] = *(uint2*)h4;
        *(uint2*)&smb[SC_CL + s * SC_P + q] = *(uint2*)l4;
        split4(bv, h4, l4);
        *(uint2*)&smb[SC_BH + s * SC_P + q] = *(uint2*)h4;
        *(uint2*)&smb[SC_BL + s * SC_P + q] = *(uint2*)l4;
    }
    // stage XT (32 p x 64 s), transposed + split
    for (int i = tid; i < 512; i += 256) {
        int s = i >> 3, q = (i & 7) * 4;
        float4 v = *(const float4*)&g_xc[(size_t)(r0 + s) * CONVD + h * HD + q];
        __nv_bfloat16 h4[4], l4[4];
        split4(v, h4, l4);
#pragma unroll
        for (int j = 0; j < 4; j++) {
            smb[SC_XH + (q + j) * SC_P + s] = h4[j];
            smb[SC_XL + (q + j) * SC_P + s] = l4[j];
        }
    }
    // stage hs (32 p x 64 n) split
    for (int i = tid; i < 512; i += 256) {
        int p = i >> 4, q = (i & 15) * 4;
        float4 v = *(const float4*)&g_hs[(size_t)cid * 2048 + p * 64 + q];
        __nv_bfloat16 h4[4], l4[4];
        split4(v, h4, l4);
        *(uint2*)&smb[SC_HH + p * SC_P + q] = *(uint2*)h4;
        *(uint2*)&smb[SC_HL + p * SC_P + q] = *(uint2*)l4;
    }
    if (tid < 64) {
        Ssm[tid] = g_S[(size_t)cid * QC + tid];
        dts[tid] = g_dtb[(size_t)(r0 + tid) * NH + h];
    }
    __syncthreads();

    uint32_t sb = smem_u32(smb);
    int mw = wid & 3, nw = wid >> 2;
    int arow = mw * 16;
    int lrow = lane & 15, lk = (lane >> 4) << 3;
    int brow = (lane & 7) + ((lane >> 4) & 1) * 8;
    int bk = ((lane >> 3) & 1) << 3;

    // --- phase 1: G = C.B^T (contraction over n), warp tile 16t x 32s ---
    float accg[4][4] = {};
#pragma unroll
    for (int kf = 0; kf < 4; kf++) {
        int k0 = kf << 4;
        uint32_t ch[4], cl[4];
        uint32_t ad = sb + (uint32_t)(((arow + lrow) * SC_P + k0 + lk) * 2);
        LDSM4(ch, ad + SC_CH * 2);
        LDSM4(cl, ad + SC_CL * 2);
        uint32_t bh2[2][4], bl2[2][4];
#pragma unroll
        for (int ng = 0; ng < 2; ng++) {
            uint32_t ad2 = sb + (uint32_t)(((nw * 32 + ng * 16 + brow) * SC_P + k0 + bk) * 2);
            LDSM4(bh2[ng], ad2 + SC_BH * 2);
            LDSM4(bl2[ng], ad2 + SC_BL * 2);
        }
#pragma unroll
        for (int nf = 0; nf < 4; nf++) {
            uint32_t* BH = &bh2[nf >> 1][(nf & 1) * 2];
            uint32_t* BL = &bl2[nf >> 1][(nf & 1) * 2];
            MMA16816(accg[nf], ch, BH[0], BH[1]);
            MMA16816(accg[nf], ch, BL[0], BL[1]);
            MMA16816(accg[nf], cl, BH[0], BH[1]);
        }
    }
    __syncthreads();   // all B reads done before M overwrites that region

    // --- phase 2: M[t][s] = mask * G * exp(St-Ss) * dt_s, split into smem ---
    int g = lane >> 2, tg = lane & 3;
    int t0 = arow + g, t1 = arow + g + 8;
    float St0 = Ssm[t0], St1 = Ssm[t1];
#pragma unroll
    for (int nf = 0; nf < 4; nf++) {
#pragma unroll
        for (int e = 0; e < 2; e++) {
            int s = nw * 32 + nf * 8 + tg * 2 + e;
            float ds = dts[s], Ss = Ssm[s];
            float m0 = (s <= t0) ? accg[nf][e]     * __expf(St0 - Ss) * ds : 0.f;
            float m1 = (s <= t1) ? accg[nf][2 + e] * __expf(St1 - Ss) * ds : 0.f;
            __nv_bfloat16 hh0, ll0, hh1, ll1;
            split_bf16(m0, hh0, ll0);
            split_bf16(m1, hh1, ll1);
            smb[SC_BH + t0 * SC_P + s] = hh0;
            smb[SC_BL + t0 * SC_P + s] = ll0;
            smb[SC_BH + t1 * SC_P + s] = hh1;
            smb[SC_BL + t1 * SC_P + s] = ll1;
        }
    }
    __syncthreads();

    // --- phase 3: Yi = M.X (over s), Yo = C.hs^T (over n); warp 16t x 16p ---
    int pw = wid >> 2;          // 0..1
    int prow = pw * 16;
    float ayi[2][4] = {}, ayo[2][4] = {};
#pragma unroll
    for (int kf = 0; kf < 4; kf++) {
        int k0 = kf << 4;
        uint32_t ad = sb + (uint32_t)(((arow + lrow) * SC_P + k0 + lk) * 2);
        uint32_t mh[4], ml[4], ch[4], cl[4];
        LDSM4(mh, ad + SC_BH * 2);
        LDSM4(ml, ad + SC_BL * 2);
        LDSM4(ch, ad + SC_CH * 2);
        LDSM4(cl, ad + SC_CL * 2);
        uint32_t ad2 = sb + (uint32_t)(((prow + brow) * SC_P + k0 + bk) * 2);
        uint32_t xh[4], xl[4], hh2[4], hl2[4];
        LDSM4(xh, ad2 + SC_XH * 2);
        LDSM4(xl, ad2 + SC_XL * 2);
        LDSM4(hh2, ad2 + SC_HH * 2);
        LDSM4(hl2, ad2 + SC_HL * 2);
#pragma unroll
        for (int nf = 0; nf < 2; nf++) {
            uint32_t* XH = &xh[nf * 2];  uint32_t* XL = &xl[nf * 2];
            uint32_t* HH = &hh2[nf * 2]; uint32_t* HL = &hl2[nf * 2];
            MMA16816(ayi[nf], mh, XH[0], XH[1]);
            MMA16816(ayi[nf], mh, XL[0], XL[1]);
            MMA16816(ayi[nf], ml, XH[0], XH[1]);
            MMA16816(ayo[nf], ch, HH[0], HH[1]);
            MMA16816(ayo[nf], ch, HL[0], HL[1]);
            MMA16816(ayo[nf], cl, HH[0], HH[1]);
        }
    }

    // --- epilogue ---
    float eS0 = __expf(St0), eS1 = __expf(St1);
#pragma unroll
    for (int nf = 0; nf < 2; nf++) {
        int p = prow + nf * 8 + tg * 2;
        float xv00 = __bfloat162float(smb[SC_XH + p * SC_P + t0])
                   + __bfloat162float(smb[SC_XL + p * SC_P + t0]);
        float xv01 = __bfloat162float(smb[SC_XH + (p + 1) * SC_P + t0])
                   + __bfloat162float(smb[SC_XL + (p + 1) * SC_P + t0]);
        float xv10 = __bfloat162float(smb[SC_XH + p * SC_P + t1])
                   + __bfloat162float(smb[SC_XL + p * SC_P + t1]);
        float xv11 = __bfloat162float(smb[SC_XH + (p + 1) * SC_P + t1])
                   + __bfloat162float(smb[SC_XL + (p + 1) * SC_P + t1]);
        *(float2*)&g_y[(size_t)(r0 + t0) * DINNER + h * HD + p] =
            make_float2(ayi[nf][0] + eS0 * ayo[nf][0] + Dh * xv00,
                        ayi[nf][1] + eS0 * ayo[nf][1] + Dh * xv01);
        *(float2*)&g_y[(size_t)(r0 + t1) * DINNER + h * HD + p] =
            make_float2(ayi[nf][2] + eS1 * ayo[nf][2] + Dh * xv10,
                        ayi[nf][3] + eS1 * ayo[nf][3] + Dh * xv11);
    }
}

// ---------------- K4a: gating + gated RMSNorm (warp/row) --------------------
__global__ void k_gate(const float* __restrict__ gw) {
    int r    = blockIdx.x * 8 + (threadIdx.x >> 5);
    int lane = threadIdx.x & 31;
    float4 y0 = *(const float4*)&g_y[(size_t)r * DINNER + lane * 4];
    float4 y1 = *(const float4*)&g_y[(size_t)r * DINNER + 128 + lane * 4];
    float4 z0 = *(const float4*)&g_zx[(size_t)r * DPROJ + lane * 4];
    float4 z1 = *(const float4*)&g_zx[(size_t)r * DPROJ + 128 + lane * 4];
    float gv[8];
    gv[0] = y0.x * (z0.x / (1.f + __expf(-z0.x)));
    gv[1] = y0.y * (z0.y / (1.f + __expf(-z0.y)));
    gv[2] = y0.z * (z0.z / (1.f + __expf(-z0.z)));
    gv[3] = y0.w * (z0.w / (1.f + __expf(-z0.w)));
    gv[4] = y1.x * (z1.x / (1.f + __expf(-z1.x)));
    gv[5] = y1.y * (z1.y / (1.f + __expf(-z1.y)));
    gv[6] = y1.z * (z1.z / (1.f + __expf(-z1.z)));
    gv[7] = y1.w * (z1.w / (1.f + __expf(-z1.w)));
    float ss = 0.f;
#pragma unroll
    for (int j = 0; j < 8; j++) ss += gv[j] * gv[j];
#pragma unroll
    for (int o = 16; o; o >>= 1) ss += __shfl_xor_sync(0xffffffffu, ss, o);
    float sc = rsqrtf(ss * (1.f / DINNER) + 1e-5f);
    float4 w0 = *(const float4*)&gw[lane * 4];
    float4 w1 = *(const float4*)&gw[128 + lane * 4];
    float wv[8] = {w0.x, w0.y, w0.z, w0.w, w1.x, w1.y, w1.z, w1.w};
    __nv_bfloat16 h[8], l[8];
#pragma unroll
    for (int j = 0; j < 8; j++) split_bf16(gv[j] * sc * wv[j], h[j], l[j]);
    *(uint2*)&g_gh[(size_t)r * DINNER + lane * 4]       = *(uint2*)&h[0];
    *(uint2*)&g_gh[(size_t)r * DINNER + 128 + lane * 4] = *(uint2*)&h[4];
    *(uint2*)&g_gl[(size_t)r * DINNER + lane * 4]       = *(uint2*)&l[0];
    *(uint2*)&g_gl[(size_t)r * DINNER + 128 + lane * 4] = *(uint2*)&l[4];
}

// ---------------- K4b: out_proj HMMA bf16x3 + residual ----------------------
#define OP_AH 0
#define OP_AL 17408
#define OP_BH 34816
#define OP_BL 52224
#define OP_TOT 69632
__global__ void __launch_bounds__(256, 1) k_outproj_mma(const float* __restrict__ x,
                                                        float* __restrict__ out) {
    extern __shared__ __align__(16) __nv_bfloat16 smb[];
    int tid = threadIdx.x, wid = tid >> 5, lane = tid & 31;
    int rowBase = blockIdx.x * 128;
    uint32_t sb = smem_u32(smb);
    int mw = wid & 3, nw = wid >> 2;
    int arow = mw * 32, ncol = nw * 64;
    float acc[2][8][4] = {};
    int lrow = lane & 15, lk = (lane >> 4) << 3;
    int brow = (lane & 7) + ((lane >> 4) & 1) * 8;
    int bk = ((lane >> 3) & 1) << 3;

    for (int kc = 0; kc < 2; kc++) {
        if (kc) __syncthreads();
        for (int i = tid; i < 2048; i += 256) {
            int r = i >> 4, c = (i & 15) << 3;
            size_t ao = (size_t)(rowBase + r) * DINNER + kc * 128 + c;
            *(uint4*)&smb[OP_AH + r * 136 + c] = *(const uint4*)(g_gh + ao);
            *(uint4*)&smb[OP_AL + r * 136 + c] = *(const uint4*)(g_gl + ao);
            size_t bo = (size_t)r * DINNER + kc * 128 + c;
            *(uint4*)&smb[OP_BH + r * 136 + c] = *(const uint4*)(g_woh + bo);
            *(uint4*)&smb[OP_BL + r * 136 + c] = *(const uint4*)(g_wol + bo);
        }
        __syncthreads();
#pragma unroll
        for (int kf = 0; kf < 8; kf++) {
            int k0 = kf << 4;
            uint32_t ah[2][4], al[2][4];
#pragma unroll
            for (int mi = 0; mi < 2; mi++) {
                uint32_t ad = sb + (uint32_t)(((arow + mi * 16 + lrow) * 136 + k0 + lk) * 2);
                LDSM4(ah[mi], ad + OP_AH * 2);
                LDSM4(al[mi], ad + OP_AL * 2);
            }
            uint32_t bh[4][4], bl[4][4];
#pragma unroll
            for (int ng = 0; ng < 4; ng++) {
                uint32_t ad = sb + (uint32_t)(((ncol + ng * 16 + brow) * 136 + k0 + bk) * 2);
                LDSM4(bh[ng], ad + OP_BH * 2);
                LDSM4(bl[ng], ad + OP_BL * 2);
            }
#pragma unroll
            for (int mi = 0; mi < 2; mi++)
#pragma unroll
                for (int nf = 0; nf < 8; nf++) {
                    uint32_t* BH = &bh[nf >> 1][(nf & 1) * 2];
                    uint32_t* BL = &bl[nf >> 1][(nf & 1) * 2];
                    MMA16816(acc[mi][nf], ah[mi], BH[0], BH[1]);
                    MMA16816(acc[mi][nf], ah[mi], BL[0], BL[1]);
                    MMA16816(acc[mi][nf], al[mi], BH[0], BH[1]);
                }
        }
    }
    int g = lane >> 2, tg = lane & 3;
#pragma unroll
    for (int mi = 0; mi < 2; mi++) {
        int r = rowBase + arow + mi * 16 + g;
#pragma unroll
        for (int nf = 0; nf < 8; nf++) {
            int c = ncol + nf * 8 + tg * 2;
            float2 x0 = *(const float2*)&x[(size_t)r * DMODEL + c];
            float2 x1 = *(const float2*)&x[(size_t)(r + 8) * DMODEL + c];
            *(float2*)&out[(size_t)r * DMODEL + c] =
                make_float2(acc[mi][nf][0] + x0.x, acc[mi][nf][1] + x0.y);
            *(float2*)&out[(size_t)(r + 8) * DMODEL + c] =
                make_float2(acc[mi][nf][2] + x1.x, acc[mi][nf][3] + x1.y);
        }
    }
}

extern "C" void kernel_launch(void* const* d_in, const int* in_sizes, int n_in,
                              void* d_out, int out_size) {
    const float* x          = (const float*)d_in[0];
    const float* norm_w     = (const float*)d_in[1];
    const float* in_proj_w  = (const float*)d_in[2];
    const float* conv_w     = (const float*)d_in[3];
    const float* conv_b     = (const float*)d_in[4];
    const float* dt_bias    = (const float*)d_in[5];
    const float* A_log      = (const float*)d_in[6];
    const float* D          = (const float*)d_in[7];
    const float* gnorm_w    = (const float*)d_in[8];
    const float* out_proj_w = (const float*)d_in[9];
    float* out = (float*)d_out;

    const int in_smem   = IP_TOT * 2;
    const int out_smem  = OP_TOT * 2;
    const int ssdc_smem = SC_END * 2 + 512;   // 55808 B
    cudaFuncSetAttribute(k_inproj_mma,  cudaFuncAttributeMaxDynamicSharedMemorySize, in_smem);
    cudaFuncSetAttribute(k_outproj_mma, cudaFuncAttributeMaxDynamicSharedMemorySize, out_smem);
    cudaFuncSetAttribute(k_ssd_c_mma,   cudaFuncAttributeMaxDynamicSharedMemorySize, ssdc_smem);

    k_wsplit<<<113, 256>>>(in_proj_w, out_proj_w);
    k_rmsnorm<<<RTOT / 8, 256>>>(x, norm_w);
    k_inproj_mma<<<dim3(RTOT / 128, 7), 256, in_smem>>>();
    k_dt<<<RTOT / 2, 256>>>(in_proj_w, dt_bias);
    k_conv2<<<dim3(RTOT / 32, 3), 128>>>(conv_w, conv_b);
    k_ssd_a<<<NCID, 128>>>(A_log);
    k_ssd_b<<<NBATCH * NH * 2, 256>>>();
    k_ssd_c_mma<<<NCID, 256, ssdc_smem>>>(D);
    k_gate<<<RTOT / 8, 256>>>(gnorm_w);
    k_outproj_mma<<<RTOT / 128, 256, out_smem>>>(x, out);
}

// round 7
// speedup vs baseline: 2.6865x; 1.1436x over previous
#include <cuda_runtime.h>
#include <cuda_bf16.h>
#include <cstdint>

#define RTOT   32768
#define LSEQ   4096
#define NBATCH 8
#define DMODEL 128
#define DPROJ  648
#define DINNER 256
#define CONVD  384
#define NH     8
#define HD     32
#define QC     64
#define NCHK   (LSEQ/QC)
#define NCID   (NBATCH*NH*NCHK)

// ---------------- scratch (device globals) ----------------------------------
__device__ __align__(16) float g_zx [(size_t)RTOT * DPROJ];
__device__ __align__(16) float g_xc [RTOT * CONVD];
__device__ __align__(16) float g_dtb[RTOT * NH];
__device__ __align__(16) float g_y  [RTOT * DINNER];
__device__ __align__(16) float g_U  [(size_t)NCID * 2048];
__device__ __align__(16) float g_hs [(size_t)NCID * 2048];
__device__ __align__(16) float g_S  [(size_t)NCID * QC];
__device__ __align__(16) float g_T  [NCID];
__device__ __align__(16) __nv_bfloat16 g_ah [RTOT * DMODEL];
__device__ __align__(16) __nv_bfloat16 g_al [RTOT * DMODEL];
__device__ __align__(16) __nv_bfloat16 g_wih[672 * DMODEL];
__device__ __align__(16) __nv_bfloat16 g_wil[672 * DMODEL];
__device__ __align__(16) __nv_bfloat16 g_gh [RTOT * DINNER];
__device__ __align__(16) __nv_bfloat16 g_gl [RTOT * DINNER];
__device__ __align__(16) __nv_bfloat16 g_woh[DMODEL * DINNER];
__device__ __align__(16) __nv_bfloat16 g_wol[DMODEL * DINNER];
// -----------------------------------------------------------------------------

// ---- warp MMA helpers ----
static __device__ __forceinline__ uint32_t smem_u32(const void* p) {
    uint32_t a;
    asm("{ .reg .u64 t; cvta.to.shared.u64 t, %1; cvt.u32.u64 %0, t; }"
        : "=r"(a) : "l"(p));
    return a;
}
#define LDSM4(r, addr) \
    asm volatile("ldmatrix.sync.aligned.m8n8.x4.shared.b16 {%0,%1,%2,%3}, [%4];" \
        : "=r"((r)[0]), "=r"((r)[1]), "=r"((r)[2]), "=r"((r)[3]) : "r"(addr))
#define LDSM4T(r, addr) \
    asm volatile("ldmatrix.sync.aligned.m8n8.x4.trans.shared.b16 {%0,%1,%2,%3}, [%4];" \
        : "=r"((r)[0]), "=r"((r)[1]), "=r"((r)[2]), "=r"((r)[3]) : "r"(addr))
#define MMA16816(d, a, b0, b1) \
    asm volatile("mma.sync.aligned.m16n8k16.row.col.f32.bf16.bf16.f32 " \
        "{%0,%1,%2,%3}, {%4,%5,%6,%7}, {%8,%9}, {%0,%1,%2,%3};" \
        : "+f"((d)[0]), "+f"((d)[1]), "+f"((d)[2]), "+f"((d)[3]) \
        : "r"((a)[0]), "r"((a)[1]), "r"((a)[2]), "r"((a)[3]), "r"(b0), "r"(b1))

static __device__ __forceinline__ void split_bf16(float v, __nv_bfloat16& h,
                                                  __nv_bfloat16& l) {
    h = __float2bfloat16(v);
    l = __float2bfloat16(v - __bfloat162float(h));
}
static __device__ __forceinline__ void split4(float4 v, __nv_bfloat16* h,
                                              __nv_bfloat16* l) {
    split_bf16(v.x, h[0], l[0]); split_bf16(v.y, h[1], l[1]);
    split_bf16(v.z, h[2], l[2]); split_bf16(v.w, h[3], l[3]);
}

// ---------------- K_w: one-shot weight split -------------------------------
__global__ void k_wsplit(const float* __restrict__ Wi, const float* __restrict__ Wo) {
    int idx = blockIdx.x * 256 + threadIdx.x;
    const int NWI = DPROJ * DMODEL / 4;
    const int NWO = DMODEL * DINNER / 4;
    if (idx < NWI) {
        float4 v = ((const float4*)Wi)[idx];
        __nv_bfloat16 h[4], l[4];
        split4(v, h, l);
        ((uint2*)g_wih)[idx] = *(uint2*)h;
        ((uint2*)g_wil)[idx] = *(uint2*)l;
    } else if (idx < NWI + NWO) {
        int j = idx - NWI;
        float4 v = ((const float4*)Wo)[j];
        __nv_bfloat16 h[4], l[4];
        split4(v, h, l);
        ((uint2*)g_woh)[j] = *(uint2*)h;
        ((uint2*)g_wol)[j] = *(uint2*)l;
    }
}

// ---------------- K0: RMSNorm -> bf16 hi/lo splits --------------------------
__global__ void k_rmsnorm(const float* __restrict__ x, const float* __restrict__ w) {
    int row  = blockIdx.x * 8 + (threadIdx.x >> 5);
    int lane = threadIdx.x & 31;
    float4 v = ((const float4*)(x + (size_t)row * DMODEL))[lane];
    float ss = v.x * v.x + v.y * v.y + v.z * v.z + v.w * v.w;
#pragma unroll
    for (int o = 16; o; o >>= 1) ss += __shfl_xor_sync(0xffffffffu, ss, o);
    float sc = rsqrtf(ss * (1.f / DMODEL) + 1e-5f);
    float4 wv = ((const float4*)w)[lane];
    float4 o4;
    o4.x = v.x * sc * wv.x; o4.y = v.y * sc * wv.y;
    o4.z = v.z * sc * wv.z; o4.w = v.w * sc * wv.w;
    __nv_bfloat16 h[4], l[4];
    split4(o4, h, l);
    ((uint2*)(g_ah + (size_t)row * DMODEL))[lane] = *(uint2*)h;
    ((uint2*)(g_al + (size_t)row * DMODEL))[lane] = *(uint2*)l;
}

// ---------------- K1: in_proj GEMM via HMMA bf16x3, tile 128x96, K=128 ------
#define IP_AH 0
#define IP_AL 17408
#define IP_BH 34816
#define IP_BL 47872
#define IP_TOT 60928
__global__ void __launch_bounds__(256, 1) k_inproj_mma() {
    extern __shared__ __align__(16) __nv_bfloat16 smb[];
    int tid = threadIdx.x, wid = tid >> 5, lane = tid & 31;
    int rowBase = blockIdx.x * 128;
    int colBase = blockIdx.y * 96;

    for (int i = tid; i < 2048; i += 256) {
        int r = i >> 4, c = (i & 15) << 3;
        *(uint4*)&smb[IP_AH + r * 136 + c] =
            *(const uint4*)(g_ah + (size_t)(rowBase + r) * DMODEL + c);
        *(uint4*)&smb[IP_AL + r * 136 + c] =
            *(const uint4*)(g_al + (size_t)(rowBase + r) * DMODEL + c);
    }
    for (int i = tid; i < 1536; i += 256) {
        int r = i >> 4, c = (i & 15) << 3;
        *(uint4*)&smb[IP_BH + r * 136 + c] =
            *(const uint4*)(g_wih + (size_t)(colBase + r) * DMODEL + c);
        *(uint4*)&smb[IP_BL + r * 136 + c] =
            *(const uint4*)(g_wil + (size_t)(colBase + r) * DMODEL + c);
    }
    __syncthreads();

    uint32_t sb = smem_u32(smb);
    int mw = wid & 3, nw = wid >> 2;
    int arow = mw * 32, ncol = nw * 48;
    float acc[2][6][4] = {};
    int lrow = lane & 15, lk = (lane >> 4) << 3;
    int brow = (lane & 7) + ((lane >> 4) & 1) * 8;
    int bk = ((lane >> 3) & 1) << 3;
#pragma unroll
    for (int kf = 0; kf < 8; kf++) {
        int k0 = kf << 4;
        uint32_t ah[2][4], al[2][4];
#pragma unroll
        for (int mi = 0; mi < 2; mi++) {
            uint32_t ad = sb + (uint32_t)(((arow + mi * 16 + lrow) * 136 + k0 + lk) * 2);
            LDSM4(ah[mi], ad + IP_AH * 2);
            LDSM4(al[mi], ad + IP_AL * 2);
        }
        uint32_t bh[3][4], bl[3][4];
#pragma unroll
        for (int ng = 0; ng < 3; ng++) {
            uint32_t ad = sb + (uint32_t)(((ncol + ng * 16 + brow) * 136 + k0 + bk) * 2);
            LDSM4(bh[ng], ad + IP_BH * 2);
            LDSM4(bl[ng], ad + IP_BL * 2);
        }
#pragma unroll
        for (int mi = 0; mi < 2; mi++)
#pragma unroll
            for (int nf = 0; nf < 6; nf++) {
                uint32_t* BH = &bh[nf >> 1][(nf & 1) * 2];
                uint32_t* BL = &bl[nf >> 1][(nf & 1) * 2];
                MMA16816(acc[mi][nf], ah[mi], BH[0], BH[1]);
                MMA16816(acc[mi][nf], ah[mi], BL[0], BL[1]);
                MMA16816(acc[mi][nf], al[mi], BH[0], BH[1]);
            }
    }
    int g = lane >> 2, tg = lane & 3;
#pragma unroll
    for (int mi = 0; mi < 2; mi++) {
        int r = rowBase + arow + mi * 16 + g;
#pragma unroll
        for (int nf = 0; nf < 6; nf++) {
            int c = colBase + ncol + nf * 8 + tg * 2;
            if (c < DPROJ) {
                *(float2*)&g_zx[(size_t)r * DPROJ + c] =
                    make_float2(acc[mi][nf][0], acc[mi][nf][1]);
                *(float2*)&g_zx[(size_t)(r + 8) * DPROJ + c] =
                    make_float2(acc[mi][nf][2], acc[mi][nf][3]);
            }
        }
    }
}

// ---------------- K2: conv(K=4)+SiLU, sliding-window ------------------------
__global__ void k_conv2(const float* __restrict__ cw, const float* __restrict__ cb) {
    int c  = blockIdx.y * 128 + threadIdx.x;
    int r0 = blockIdx.x * 32;
    bool hist = (r0 & (LSEQ - 1)) != 0;
    float w0 = cw[c * 4 + 0], w1 = cw[c * 4 + 1];
    float w2 = cw[c * 4 + 2], w3 = cw[c * 4 + 3];
    float bias = cb[c];
    const float* src = g_zx + 256 + c;
    float* dst = g_xc + c;
    float x0 = hist ? src[(size_t)(r0 - 3) * DPROJ] : 0.f;
    float x1 = hist ? src[(size_t)(r0 - 2) * DPROJ] : 0.f;
    float x2 = hist ? src[(size_t)(r0 - 1) * DPROJ] : 0.f;
#pragma unroll 8
    for (int s = 0; s < 32; s++) {
        int r = r0 + s;
        float x3 = src[(size_t)r * DPROJ];
        float acc = bias + w0 * x0 + w1 * x1 + w2 * x2 + w3 * x3;
        dst[(size_t)r * CONVD] = acc / (1.f + __expf(-acc));
        x0 = x1; x1 = x2; x2 = x3;
    }
}

// ---------------- SSD pass A via HMMA bf16x3 --------------------------------
// U[p][n] = sum_s (exp(T-S_s) dt_s x[s][p]) B[s][n]; also computes dt, S, T.
// X staged (s,p) pitch 40; B staged (s,n) pitch 72; both consumed via
// ldmatrix.trans (A-frag groups: (s0,p0),(s0,p8),(s8,p0),(s8,p8)).
#define SA_BH 0
#define SA_BL 4608
#define SA_XH 9216
#define SA_XL 11776
#define SA_END 14336
__global__ void __launch_bounds__(256) k_ssd_a_mma(const float* __restrict__ A_log,
                                                   const float* __restrict__ dtb) {
    __shared__ __align__(16) __nv_bfloat16 smb[SA_END];
    __shared__ float sdt[64], sS[64], ssc[64];
    int tid = threadIdx.x;
    int cid = blockIdx.x;
    int bh = cid >> 6, c = cid & 63;
    int b = bh >> 3, h = bh & 7;
    int r0 = b * LSEQ + c * QC;
    float A = -__expf(A_log[h]);

    if (tid < 64) {
        float v = g_zx[(size_t)(r0 + tid) * DPROJ + 640 + h] + dtb[h];
        v = (v > 20.f) ? v : log1pf(__expf(v));
        sdt[tid] = v;
        g_dtb[(size_t)(r0 + tid) * NH + h] = v;
    }
    // stage B (64x64) split hi/lo
    for (int i = tid; i < 1024; i += 256) {
        int s = i >> 4, q = (i & 15) * 4;
        float4 bv = *(const float4*)&g_xc[(size_t)(r0 + s) * CONVD + 256 + q];
        __nv_bfloat16 h4[4], l4[4];
        split4(bv, h4, l4);
        *(uint2*)&smb[SA_BH + s * 72 + q] = *(uint2*)h4;
        *(uint2*)&smb[SA_BL + s * 72 + q] = *(uint2*)l4;
    }
    __syncthreads();
    if (tid < 64) {
        float v = sdt[tid] * A;
#pragma unroll
        for (int o = 1; o < 32; o <<= 1) {
            float u = __shfl_up_sync(0xffffffffu, v, o);
            if ((tid & 31) >= o) v += u;
        }
        sS[tid] = v;
    }
    __syncthreads();
    if (tid >= 32 && tid < 64) sS[tid] += sS[31];
    __syncthreads();
    float T = sS[63];
    if (tid < 64) {
        float sv = sS[tid];
        g_S[(size_t)cid * QC + tid] = sv;
        ssc[tid] = __expf(T - sv) * sdt[tid];
    }
    if (tid == 0) g_T[cid] = T;
    __syncthreads();
    // stage scaled X (s,p) split hi/lo
    for (int i = tid; i < 512; i += 256) {
        int s = i >> 3, q = (i & 7) * 4;
        float4 v = *(const float4*)&g_xc[(size_t)(r0 + s) * CONVD + h * HD + q];
        float sc = ssc[s];
        v.x *= sc; v.y *= sc; v.z *= sc; v.w *= sc;
        __nv_bfloat16 h4[4], l4[4];
        split4(v, h4, l4);
        *(uint2*)&smb[SA_XH + s * 40 + q] = *(uint2*)h4;
        *(uint2*)&smb[SA_XL + s * 40 + q] = *(uint2*)l4;
    }
    __syncthreads();

    uint32_t sb = smem_u32(smb);
    int wid = tid >> 5, lane = tid & 31;
    int mw = wid & 1, nw = wid >> 1;
    int gidx = lane >> 3;
    int a_soff = (gidx >> 1) * 8, a_poff = (gidx & 1) * 8;
    int b_soff = ((lane >> 3) & 1) * 8, b_noff = (lane >> 4) * 8;
    float acc[2][4] = {};
#pragma unroll
    for (int kf = 0; kf < 4; kf++) {
        int k0 = kf << 4;
        uint32_t xh4[4], xl4[4], bh4[4], bl4[4];
        uint32_t ax = sb + (uint32_t)((SA_XH + (k0 + a_soff + (lane & 7)) * 40
                                       + mw * 16 + a_poff) * 2);
        LDSM4T(xh4, ax);
        LDSM4T(xl4, ax + (SA_XL - SA_XH) * 2);
        uint32_t bad = sb + (uint32_t)((SA_BH + (k0 + b_soff + (lane & 7)) * 72
                                        + nw * 16 + b_noff) * 2);
        LDSM4T(bh4, bad);
        LDSM4T(bl4, bad + (SA_BL - SA_BH) * 2);
#pragma unroll
        for (int nf = 0; nf < 2; nf++) {
            MMA16816(acc[nf], xh4, bh4[nf * 2], bh4[nf * 2 + 1]);
            MMA16816(acc[nf], xh4, bl4[nf * 2], bl4[nf * 2 + 1]);
            MMA16816(acc[nf], xl4, bh4[nf * 2], bh4[nf * 2 + 1]);
        }
    }
    int g = lane >> 2, tg = lane & 3;
    size_t ub = (size_t)cid * 2048;
#pragma unroll
    for (int nf = 0; nf < 2; nf++) {
        int p = mw * 16 + g, n = nw * 16 + nf * 8 + tg * 2;
        *(float2*)&g_U[ub + p * 64 + n]       = make_float2(acc[nf][0], acc[nf][1]);
        *(float2*)&g_U[ub + (p + 8) * 64 + n] = make_float2(acc[nf][2], acc[nf][3]);
    }
}

// ---------------- SSD pass B ------------------------------------------------
__global__ void k_ssd_b() {
    __shared__ float sT[NCHK];
    int bh   = blockIdx.x >> 1;
    int half = blockIdx.x & 1;
    int tid  = threadIdx.x;  // 256
    size_t base = (size_t)bh * NCHK;
    if (tid < NCHK) sT[tid] = __expf(g_T[base + tid]);
    __syncthreads();
    size_t o0 = base * 2048 + half * 1024 + tid * 4;
    float4 h0 = make_float4(0.f, 0.f, 0.f, 0.f);
    float4 u0 = *(const float4*)&g_U[o0];
    for (int c = 0; c < NCHK; c++) {
        size_t off = (size_t)c * 2048;
        *(float4*)&g_hs[o0 + off] = h0;
        float e = sT[c];
        float4 n0 = make_float4(0.f, 0.f, 0.f, 0.f);
        if (c + 1 < NCHK) n0 = *(const float4*)&g_U[o0 + off + 2048];
        h0.x = e * h0.x + u0.x; h0.y = e * h0.y + u0.y;
        h0.z = e * h0.z + u0.z; h0.w = e * h0.w + u0.w;
        u0 = n0;
    }
}

// ---------------- SSD pass C via HMMA bf16x3 --------------------------------
#define SC_P  72
#define SC_CH 0
#define SC_CL 4608
#define SC_BH 9216     /* later reused as M hi */
#define SC_BL 13824    /* later reused as M lo */
#define SC_XH 18432    /* X (s,p) pitch 40 */
#define SC_XL 20992
#define SC_HH 23552    /* hs (p,n) pitch 72 */
#define SC_HL 25856
#define SC_END 28160
__global__ void __launch_bounds__(256, 2) k_ssd_c_mma(const float* __restrict__ Dp) {
    extern __shared__ __align__(16) __nv_bfloat16 smb[];
    float* Ssm = (float*)(smb + SC_END);
    float* dts = Ssm + 64;
    int tid = threadIdx.x, wid = tid >> 5, lane = tid & 31;
    int cid = blockIdx.x;
    int bh = cid >> 6, c = cid & 63;
    int b = bh >> 3, h = bh & 7;
    int r0 = b * LSEQ + c * QC;
    float Dh = Dp[h];

    for (int i = tid; i < 1024; i += 256) {
        int s = i >> 4, q = (i & 15) * 4;
        float4 cv = *(const float4*)&g_xc[(size_t)(r0 + s) * CONVD + 320 + q];
        float4 bv = *(const float4*)&g_xc[(size_t)(r0 + s) * CONVD + 256 + q];
        __nv_bfloat16 h4[4], l4[4];
        split4(cv, h4, l4);
        *(uint2*)&smb[SC_CH + s * SC_P + q] = *(uint2*)h4;
        *(uint2*)&smb[SC_CL + s * SC_P + q] = *(uint2*)l4;
        split4(bv, h4, l4);
        *(uint2*)&smb[SC_BH + s * SC_P + q] = *(uint2*)h4;
        *(uint2*)&smb[SC_BL + s * SC_P + q] = *(uint2*)l4;
    }
    // X (s,p) pitch 40 (consumed via ldmatrix.trans)
    for (int i = tid; i < 512; i += 256) {
        int s = i >> 3, q = (i & 7) * 4;
        float4 v = *(const float4*)&g_xc[(size_t)(r0 + s) * CONVD + h * HD + q];
        __nv_bfloat16 h4[4], l4[4];
        split4(v, h4, l4);
        *(uint2*)&smb[SC_XH + s * 40 + q] = *(uint2*)h4;
        *(uint2*)&smb[SC_XL + s * 40 + q] = *(uint2*)l4;
    }
    for (int i = tid; i < 512; i += 256) {
        int p = i >> 4, q = (i & 15) * 4;
        float4 v = *(const float4*)&g_hs[(size_t)cid * 2048 + p * 64 + q];
        __nv_bfloat16 h4[4], l4[4];
        split4(v, h4, l4);
        *(uint2*)&smb[SC_HH + p * SC_P + q] = *(uint2*)h4;
        *(uint2*)&smb[SC_HL + p * SC_P + q] = *(uint2*)l4;
    }
    if (tid < 64) {
        Ssm[tid] = g_S[(size_t)cid * QC + tid];
        dts[tid] = g_dtb[(size_t)(r0 + tid) * NH + h];
    }
    __syncthreads();

    uint32_t sb = smem_u32(smb);
    int mw = wid & 3, nw = wid >> 2;
    int arow = mw * 16;
    int lrow = lane & 15, lk = (lane >> 4) << 3;
    int brow = (lane & 7) + ((lane >> 4) & 1) * 8;
    int bk = ((lane >> 3) & 1) << 3;
    int b_soff = ((lane >> 3) & 1) * 8, b_noff = (lane >> 4) * 8;

    // --- phase 1: G = C.B^T (contraction over n), warp tile 16t x 32s ---
    float accg[4][4] = {};
#pragma unroll
    for (int kf = 0; kf < 4; kf++) {
        int k0 = kf << 4;
        uint32_t ch[4], cl[4];
        uint32_t ad = sb + (uint32_t)(((arow + lrow) * SC_P + k0 + lk) * 2);
        LDSM4(ch, ad + SC_CH * 2);
        LDSM4(cl, ad + SC_CL * 2);
        uint32_t bh2[2][4], bl2[2][4];
#pragma unroll
        for (int ng = 0; ng < 2; ng++) {
            uint32_t ad2 = sb + (uint32_t)(((nw * 32 + ng * 16 + brow) * SC_P + k0 + bk) * 2);
            LDSM4(bh2[ng], ad2 + SC_BH * 2);
            LDSM4(bl2[ng], ad2 + SC_BL * 2);
        }
#pragma unroll
        for (int nf = 0; nf < 4; nf++) {
            uint32_t* BH = &bh2[nf >> 1][(nf & 1) * 2];
            uint32_t* BL = &bl2[nf >> 1][(nf & 1) * 2];
            MMA16816(accg[nf], ch, BH[0], BH[1]);
            MMA16816(accg[nf], ch, BL[0], BL[1]);
            MMA16816(accg[nf], cl, BH[0], BH[1]);
        }
    }
    __syncthreads();

    // --- phase 2: M[t][s] = mask * G * exp(St-Ss) * dt_s ---
    int g = lane >> 2, tg = lane & 3;
    int t0 = arow + g, t1 = arow + g + 8;
    float St0 = Ssm[t0], St1 = Ssm[t1];
#pragma unroll
    for (int nf = 0; nf < 4; nf++) {
#pragma unroll
        for (int e = 0; e < 2; e++) {
            int s = nw * 32 + nf * 8 + tg * 2 + e;
            float ds = dts[s], Ss = Ssm[s];
            float m0 = (s <= t0) ? accg[nf][e]     * __expf(St0 - Ss) * ds : 0.f;
            float m1 = (s <= t1) ? accg[nf][2 + e] * __expf(St1 - Ss) * ds : 0.f;
            __nv_bfloat16 hh0, ll0, hh1, ll1;
            split_bf16(m0, hh0, ll0);
            split_bf16(m1, hh1, ll1);
            smb[SC_BH + t0 * SC_P + s] = hh0;
            smb[SC_BL + t0 * SC_P + s] = ll0;
            smb[SC_BH + t1 * SC_P + s] = hh1;
            smb[SC_BL + t1 * SC_P + s] = ll1;
        }
    }
    __syncthreads();

    // --- phase 3: Yi = M.X (over s, X via trans), Yo = C.hs^T (over n) ---
    int pw = wid >> 2;
    int prow = pw * 16;
    float ayi[2][4] = {}, ayo[2][4] = {};
#pragma unroll
    for (int kf = 0; kf < 4; kf++) {
        int k0 = kf << 4;
        uint32_t ad = sb + (uint32_t)(((arow + lrow) * SC_P + k0 + lk) * 2);
        uint32_t mh[4], ml[4], ch[4], cl[4];
        LDSM4(mh, ad + SC_BH * 2);
        LDSM4(ml, ad + SC_BL * 2);
        LDSM4(ch, ad + SC_CH * 2);
        LDSM4(cl, ad + SC_CL * 2);
        uint32_t xh[4], xl[4], hh2[4], hl2[4];
        uint32_t adx = sb + (uint32_t)((SC_XH + (k0 + b_soff + (lane & 7)) * 40
                                        + prow + b_noff) * 2);
        LDSM4T(xh, adx);
        LDSM4T(xl, adx + (SC_XL - SC_XH) * 2);
        uint32_t adh = sb + (uint32_t)(((prow + brow) * SC_P + k0 + bk) * 2);
        LDSM4(hh2, adh + SC_HH * 2);
        LDSM4(hl2, adh + SC_HL * 2);
#pragma unroll
        for (int nf = 0; nf < 2; nf++) {
            uint32_t* XH = &xh[nf * 2];  uint32_t* XL = &xl[nf * 2];
            uint32_t* HH = &hh2[nf * 2]; uint32_t* HL = &hl2[nf * 2];
            MMA16816(ayi[nf], mh, XH[0], XH[1]);
            MMA16816(ayi[nf], mh, XL[0], XL[1]);
            MMA16816(ayi[nf], ml, XH[0], XH[1]);
            MMA16816(ayo[nf], ch, HH[0], HH[1]);
            MMA16816(ayo[nf], ch, HL[0], HL[1]);
            MMA16816(ayo[nf], cl, HH[0], HH[1]);
        }
    }

    // --- epilogue ---
    float eS0 = __expf(St0), eS1 = __expf(St1);
#pragma unroll
    for (int nf = 0; nf < 2; nf++) {
        int p = prow + nf * 8 + tg * 2;
        float xv00 = __bfloat162float(smb[SC_XH + t0 * 40 + p])
                   + __bfloat162float(smb[SC_XL + t0 * 40 + p]);
        float xv01 = __bfloat162float(smb[SC_XH + t0 * 40 + p + 1])
                   + __bfloat162float(smb[SC_XL + t0 * 40 + p + 1]);
        float xv10 = __bfloat162float(smb[SC_XH + t1 * 40 + p])
                   + __bfloat162float(smb[SC_XL + t1 * 40 + p]);
        float xv11 = __bfloat162float(smb[SC_XH + t1 * 40 + p + 1])
                   + __bfloat162float(smb[SC_XL + t1 * 40 + p + 1]);
        *(float2*)&g_y[(size_t)(r0 + t0) * DINNER + h * HD + p] =
            make_float2(ayi[nf][0] + eS0 * ayo[nf][0] + Dh * xv00,
                        ayi[nf][1] + eS0 * ayo[nf][1] + Dh * xv01);
        *(float2*)&g_y[(size_t)(r0 + t1) * DINNER + h * HD + p] =
            make_float2(ayi[nf][2] + eS1 * ayo[nf][2] + Dh * xv10,
                        ayi[nf][3] + eS1 * ayo[nf][3] + Dh * xv11);
    }
}

// ---------------- K4a: gating + gated RMSNorm (warp/row) --------------------
__global__ void k_gate(const float* __restrict__ gw) {
    int r    = blockIdx.x * 8 + (threadIdx.x >> 5);
    int lane = threadIdx.x & 31;
    float4 y0 = *(const float4*)&g_y[(size_t)r * DINNER + lane * 4];
    float4 y1 = *(const float4*)&g_y[(size_t)r * DINNER + 128 + lane * 4];
    float4 z0 = *(const float4*)&g_zx[(size_t)r * DPROJ + lane * 4];
    float4 z1 = *(const float4*)&g_zx[(size_t)r * DPROJ + 128 + lane * 4];
    float gv[8];
    gv[0] = y0.x * (z0.x / (1.f + __expf(-z0.x)));
    gv[1] = y0.y * (z0.y / (1.f + __expf(-z0.y)));
    gv[2] = y0.z * (z0.z / (1.f + __expf(-z0.z)));
    gv[3] = y0.w * (z0.w / (1.f + __expf(-z0.w)));
    gv[4] = y1.x * (z1.x / (1.f + __expf(-z1.x)));
    gv[5] = y1.y * (z1.y / (1.f + __expf(-z1.y)));
    gv[6] = y1.z * (z1.z / (1.f + __expf(-z1.z)));
    gv[7] = y1.w * (z1.w / (1.f + __expf(-z1.w)));
    float ss = 0.f;
#pragma unroll
    for (int j = 0; j < 8; j++) ss += gv[j] * gv[j];
#pragma unroll
    for (int o = 16; o; o >>= 1) ss += __shfl_xor_sync(0xffffffffu, ss, o);
    float sc = rsqrtf(ss * (1.f / DINNER) + 1e-5f);
    float4 w0 = *(const float4*)&gw[lane * 4];
    float4 w1 = *(const float4*)&gw[128 + lane * 4];
    float wv[8] = {w0.x, w0.y, w0.z, w0.w, w1.x, w1.y, w1.z, w1.w};
    __nv_bfloat16 h[8], l[8];
#pragma unroll
    for (int j = 0; j < 8; j++) split_bf16(gv[j] * sc * wv[j], h[j], l[j]);
    *(uint2*)&g_gh[(size_t)r * DINNER + lane * 4]       = *(uint2*)&h[0];
    *(uint2*)&g_gh[(size_t)r * DINNER + 128 + lane * 4] = *(uint2*)&h[4];
    *(uint2*)&g_gl[(size_t)r * DINNER + lane * 4]       = *(uint2*)&l[0];
    *(uint2*)&g_gl[(size_t)r * DINNER + 128 + lane * 4] = *(uint2*)&l[4];
}

// ---------------- K4b: out_proj HMMA bf16x3 + residual ----------------------
#define OP_AH 0
#define OP_AL 17408
#define OP_BH 34816
#define OP_BL 52224
#define OP_TOT 69632
__global__ void __launch_bounds__(256, 1) k_outproj_mma(const float* __restrict__ x,
                                                        float* __restrict__ out) {
    extern __shared__ __align__(16) __nv_bfloat16 smb[];
    int tid = threadIdx.x, wid = tid >> 5, lane = tid & 31;
    int rowBase = blockIdx.x * 128;
    uint32_t sb = smem_u32(smb);
    int mw = wid & 3, nw = wid >> 2;
    int arow = mw * 32, ncol = nw * 64;
    float acc[2][8][4] = {};
    int lrow = lane & 15, lk = (lane >> 4) << 3;
    int brow = (lane & 7) + ((lane >> 4) & 1) * 8;
    int bk = ((lane >> 3) & 1) << 3;

    for (int kc = 0; kc < 2; kc++) {
        if (kc) __syncthreads();
        for (int i = tid; i < 2048; i += 256) {
            int r = i >> 4, c = (i & 15) << 3;
            size_t ao = (size_t)(rowBase + r) * DINNER + kc * 128 + c;
            *(uint4*)&smb[OP_AH + r * 136 + c] = *(const uint4*)(g_gh + ao);
            *(uint4*)&smb[OP_AL + r * 136 + c] = *(const uint4*)(g_gl + ao);
            size_t bo = (size_t)r * DINNER + kc * 128 + c;
            *(uint4*)&smb[OP_BH + r * 136 + c] = *(const uint4*)(g_woh + bo);
            *(uint4*)&smb[OP_BL + r * 136 + c] = *(const uint4*)(g_wol + bo);
        }
        __syncthreads();
#pragma unroll
        for (int kf = 0; kf < 8; kf++) {
            int k0 = kf << 4;
            uint32_t ah[2][4], al[2][4];
#pragma unroll
            for (int mi = 0; mi < 2; mi++) {
                uint32_t ad = sb + (uint32_t)(((arow + mi * 16 + lrow) * 136 + k0 + lk) * 2);
                LDSM4(ah[mi], ad + OP_AH * 2);
                LDSM4(al[mi], ad + OP_AL * 2);
            }
            uint32_t bh[4][4], bl[4][4];
#pragma unroll
            for (int ng = 0; ng < 4; ng++) {
                uint32_t ad = sb + (uint32_t)(((ncol + ng * 16 + brow) * 136 + k0 + bk) * 2);
                LDSM4(bh[ng], ad + OP_BH * 2);
                LDSM4(bl[ng], ad + OP_BL * 2);
            }
#pragma unroll
            for (int mi = 0; mi < 2; mi++)
#pragma unroll
                for (int nf = 0; nf < 8; nf++) {
                    uint32_t* BH = &bh[nf >> 1][(nf & 1) * 2];
                    uint32_t* BL = &bl[nf >> 1][(nf & 1) * 2];
                    MMA16816(acc[mi][nf], ah[mi], BH[0], BH[1]);
                    MMA16816(acc[mi][nf], ah[mi], BL[0], BL[1]);
                    MMA16816(acc[mi][nf], al[mi], BH[0], BH[1]);
                }
        }
    }
    int g = lane >> 2, tg = lane & 3;
#pragma unroll
    for (int mi = 0; mi < 2; mi++) {
        int r = rowBase + arow + mi * 16 + g;
#pragma unroll
        for (int nf = 0; nf < 8; nf++) {
            int c = ncol + nf * 8 + tg * 2;
            float2 x0 = *(const float2*)&x[(size_t)r * DMODEL + c];
            float2 x1 = *(const float2*)&x[(size_t)(r + 8) * DMODEL + c];
            *(float2*)&out[(size_t)r * DMODEL + c] =
                make_float2(acc[mi][nf][0] + x0.x, acc[mi][nf][1] + x0.y);
            *(float2*)&out[(size_t)(r + 8) * DMODEL + c] =
                make_float2(acc[mi][nf][2] + x1.x, acc[mi][nf][3] + x1.y);
        }
    }
}

extern "C" void kernel_launch(void* const* d_in, const int* in_sizes, int n_in,
                              void* d_out, int out_size) {
    const float* x          = (const float*)d_in[0];
    const float* norm_w     = (const float*)d_in[1];
    const float* in_proj_w  = (const float*)d_in[2];
    const float* conv_w     = (const float*)d_in[3];
    const float* conv_b     = (const float*)d_in[4];
    const float* dt_bias    = (const float*)d_in[5];
    const float* A_log      = (const float*)d_in[6];
    const float* D          = (const float*)d_in[7];
    const float* gnorm_w    = (const float*)d_in[8];
    const float* out_proj_w = (const float*)d_in[9];
    float* out = (float*)d_out;

    const int in_smem   = IP_TOT * 2;
    const int out_smem  = OP_TOT * 2;
    const int ssdc_smem = SC_END * 2 + 512;   // 56832 B
    cudaFuncSetAttribute(k_inproj_mma,  cudaFuncAttributeMaxDynamicSharedMemorySize, in_smem);
    cudaFuncSetAttribute(k_outproj_mma, cudaFuncAttributeMaxDynamicSharedMemorySize, out_smem);
    cudaFuncSetAttribute(k_ssd_c_mma,   cudaFuncAttributeMaxDynamicSharedMemorySize, ssdc_smem);

    k_wsplit<<<113, 256>>>(in_proj_w, out_proj_w);
    k_rmsnorm<<<RTOT / 8, 256>>>(x, norm_w);
    k_inproj_mma<<<dim3(RTOT / 128, 7), 256, in_smem>>>();
    k_conv2<<<dim3(RTOT / 32, 3), 128>>>(conv_w, conv_b);
    k_ssd_a_mma<<<NCID, 256>>>(A_log, dt_bias);
    k_ssd_b<<<NBATCH * NH * 2, 256>>>();
    k_ssd_c_mma<<<NCID, 256, ssdc_smem>>>(D);
    k_gate<<<RTOT / 8, 256>>>(gnorm_w);
    k_outproj_mma<<<RTOT / 128, 256, out_smem>>>(x, out);
}

// round 8
// speedup vs baseline: 2.8322x; 1.0542x over previous
#include <cuda_runtime.h>
#include <cuda_bf16.h>
#include <cstdint>

#define RTOT   32768
#define LSEQ   4096
#define NBATCH 8
#define DMODEL 128
#define DPROJ  648
#define DINNER 256
#define CONVD  384
#define NH     8
#define HD     32
#define QC     64
#define NCHK   (LSEQ/QC)
#define NCID   (NBATCH*NH*NCHK)

// ---------------- scratch (device globals) ----------------------------------
__device__ __align__(16) float g_zx [(size_t)RTOT * DPROJ];
__device__ __align__(16) float g_xc [RTOT * CONVD];
__device__ __align__(16) float g_dtb[RTOT * NH];
__device__ __align__(16) float g_y  [RTOT * DINNER];
__device__ __align__(16) float g_U  [(size_t)NCID * 2048];
__device__ __align__(16) float g_hs [(size_t)NCID * 2048];
__device__ __align__(16) float g_S  [(size_t)NCID * QC];
__device__ __align__(16) float g_T  [NCID];
__device__ __align__(16) __nv_bfloat16 g_ah [RTOT * DMODEL];
__device__ __align__(16) __nv_bfloat16 g_al [RTOT * DMODEL];
__device__ __align__(16) __nv_bfloat16 g_wih[672 * DMODEL];
__device__ __align__(16) __nv_bfloat16 g_wil[672 * DMODEL];
__device__ __align__(16) __nv_bfloat16 g_gh [RTOT * DINNER];
__device__ __align__(16) __nv_bfloat16 g_gl [RTOT * DINNER];
__device__ __align__(16) __nv_bfloat16 g_woh[DMODEL * DINNER];
__device__ __align__(16) __nv_bfloat16 g_wol[DMODEL * DINNER];
__device__ __align__(16) __nv_bfloat16 g_wbh[64 * 4096];   // chunk-scan W hi
__device__ __align__(16) __nv_bfloat16 g_wbl[64 * 4096];   // chunk-scan W lo
// -----------------------------------------------------------------------------

// ---- warp MMA helpers ----
static __device__ __forceinline__ uint32_t smem_u32(const void* p) {
    uint32_t a;
    asm("{ .reg .u64 t; cvta.to.shared.u64 t, %1; cvt.u32.u64 %0, t; }"
        : "=r"(a) : "l"(p));
    return a;
}
#define LDSM4(r, addr) \
    asm volatile("ldmatrix.sync.aligned.m8n8.x4.shared.b16 {%0,%1,%2,%3}, [%4];" \
        : "=r"((r)[0]), "=r"((r)[1]), "=r"((r)[2]), "=r"((r)[3]) : "r"(addr))
#define LDSM4T(r, addr) \
    asm volatile("ldmatrix.sync.aligned.m8n8.x4.trans.shared.b16 {%0,%1,%2,%3}, [%4];" \
        : "=r"((r)[0]), "=r"((r)[1]), "=r"((r)[2]), "=r"((r)[3]) : "r"(addr))
#define MMA16816(d, a, b0, b1) \
    asm volatile("mma.sync.aligned.m16n8k16.row.col.f32.bf16.bf16.f32 " \
        "{%0,%1,%2,%3}, {%4,%5,%6,%7}, {%8,%9}, {%0,%1,%2,%3};" \
        : "+f"((d)[0]), "+f"((d)[1]), "+f"((d)[2]), "+f"((d)[3]) \
        : "r"((a)[0]), "r"((a)[1]), "r"((a)[2]), "r"((a)[3]), "r"(b0), "r"(b1))

static __device__ __forceinline__ void split_bf16(float v, __nv_bfloat16& h,
                                                  __nv_bfloat16& l) {
    h = __float2bfloat16(v);
    l = __float2bfloat16(v - __bfloat162float(h));
}
static __device__ __forceinline__ void split4(float4 v, __nv_bfloat16* h,
                                              __nv_bfloat16* l) {
    split_bf16(v.x, h[0], l[0]); split_bf16(v.y, h[1], l[1]);
    split_bf16(v.z, h[2], l[2]); split_bf16(v.w, h[3], l[3]);
}
static __device__ __forceinline__ float silu(float v) {
    return v / (1.f + __expf(-v));
}

// ---------------- K_w: one-shot weight split -------------------------------
__global__ void k_wsplit(const float* __restrict__ Wi, const float* __restrict__ Wo) {
    int idx = blockIdx.x * 256 + threadIdx.x;
    const int NWI = DPROJ * DMODEL / 4;
    const int NWO = DMODEL * DINNER / 4;
    if (idx < NWI) {
        float4 v = ((const float4*)Wi)[idx];
        __nv_bfloat16 h[4], l[4];
        split4(v, h, l);
        ((uint2*)g_wih)[idx] = *(uint2*)h;
        ((uint2*)g_wil)[idx] = *(uint2*)l;
    } else if (idx < NWI + NWO) {
        int j = idx - NWI;
        float4 v = ((const float4*)Wo)[j];
        __nv_bfloat16 h[4], l[4];
        split4(v, h, l);
        ((uint2*)g_woh)[j] = *(uint2*)h;
        ((uint2*)g_wol)[j] = *(uint2*)l;
    }
}

// ---------------- K0: RMSNorm -> bf16 hi/lo splits --------------------------
__global__ void k_rmsnorm(const float* __restrict__ x, const float* __restrict__ w) {
    int row  = blockIdx.x * 8 + (threadIdx.x >> 5);
    int lane = threadIdx.x & 31;
    float4 v = ((const float4*)(x + (size_t)row * DMODEL))[lane];
    float ss = v.x * v.x + v.y * v.y + v.z * v.z + v.w * v.w;
#pragma unroll
    for (int o = 16; o; o >>= 1) ss += __shfl_xor_sync(0xffffffffu, ss, o);
    float sc = rsqrtf(ss * (1.f / DMODEL) + 1e-5f);
    float4 wv = ((const float4*)w)[lane];
    float4 o4;
    o4.x = v.x * sc * wv.x; o4.y = v.y * sc * wv.y;
    o4.z = v.z * sc * wv.z; o4.w = v.w * sc * wv.w;
    __nv_bfloat16 h[4], l[4];
    split4(o4, h, l);
    ((uint2*)(g_ah + (size_t)row * DMODEL))[lane] = *(uint2*)h;
    ((uint2*)(g_al + (size_t)row * DMODEL))[lane] = *(uint2*)l;
}

// ---------------- K1: in_proj GEMM via HMMA bf16x3, tile 128x96, K=128 ------
#define IP_AH 0
#define IP_AL 17408
#define IP_BH 34816
#define IP_BL 47872
#define IP_TOT 60928
__global__ void __launch_bounds__(256, 1) k_inproj_mma() {
    extern __shared__ __align__(16) __nv_bfloat16 smb[];
    int tid = threadIdx.x, wid = tid >> 5, lane = tid & 31;
    int rowBase = blockIdx.x * 128;
    int colBase = blockIdx.y * 96;

    for (int i = tid; i < 2048; i += 256) {
        int r = i >> 4, c = (i & 15) << 3;
        *(uint4*)&smb[IP_AH + r * 136 + c] =
            *(const uint4*)(g_ah + (size_t)(rowBase + r) * DMODEL + c);
        *(uint4*)&smb[IP_AL + r * 136 + c] =
            *(const uint4*)(g_al + (size_t)(rowBase + r) * DMODEL + c);
    }
    for (int i = tid; i < 1536; i += 256) {
        int r = i >> 4, c = (i & 15) << 3;
        *(uint4*)&smb[IP_BH + r * 136 + c] =
            *(const uint4*)(g_wih + (size_t)(colBase + r) * DMODEL + c);
        *(uint4*)&smb[IP_BL + r * 136 + c] =
            *(const uint4*)(g_wil + (size_t)(colBase + r) * DMODEL + c);
    }
    __syncthreads();

    uint32_t sb = smem_u32(smb);
    int mw = wid & 3, nw = wid >> 2;
    int arow = mw * 32, ncol = nw * 48;
    float acc[2][6][4] = {};
    int lrow = lane & 15, lk = (lane >> 4) << 3;
    int brow = (lane & 7) + ((lane >> 4) & 1) * 8;
    int bk = ((lane >> 3) & 1) << 3;
#pragma unroll
    for (int kf = 0; kf < 8; kf++) {
        int k0 = kf << 4;
        uint32_t ah[2][4], al[2][4];
#pragma unroll
        for (int mi = 0; mi < 2; mi++) {
            uint32_t ad = sb + (uint32_t)(((arow + mi * 16 + lrow) * 136 + k0 + lk) * 2);
            LDSM4(ah[mi], ad + IP_AH * 2);
            LDSM4(al[mi], ad + IP_AL * 2);
        }
        uint32_t bh[3][4], bl[3][4];
#pragma unroll
        for (int ng = 0; ng < 3; ng++) {
            uint32_t ad = sb + (uint32_t)(((ncol + ng * 16 + brow) * 136 + k0 + bk) * 2);
            LDSM4(bh[ng], ad + IP_BH * 2);
            LDSM4(bl[ng], ad + IP_BL * 2);
        }
#pragma unroll
        for (int mi = 0; mi < 2; mi++)
#pragma unroll
            for (int nf = 0; nf < 6; nf++) {
                uint32_t* BH = &bh[nf >> 1][(nf & 1) * 2];
                uint32_t* BL = &bl[nf >> 1][(nf & 1) * 2];
                MMA16816(acc[mi][nf], ah[mi], BH[0], BH[1]);
                MMA16816(acc[mi][nf], ah[mi], BL[0], BL[1]);
                MMA16816(acc[mi][nf], al[mi], BH[0], BH[1]);
            }
    }
    int g = lane >> 2, tg = lane & 3;
#pragma unroll
    for (int mi = 0; mi < 2; mi++) {
        int r = rowBase + arow + mi * 16 + g;
#pragma unroll
        for (int nf = 0; nf < 6; nf++) {
            int c = colBase + ncol + nf * 8 + tg * 2;
            if (c < DPROJ) {
                *(float2*)&g_zx[(size_t)r * DPROJ + c] =
                    make_float2(acc[mi][nf][0], acc[mi][nf][1]);
                *(float2*)&g_zx[(size_t)(r + 8) * DPROJ + c] =
                    make_float2(acc[mi][nf][2], acc[mi][nf][3]);
            }
        }
    }
}

// ---------------- K2: conv(K=4)+SiLU, float4 sliding-window -----------------
// block 384: tid%96 -> channel quad, tid/96 -> 8-row strip; grid 1024.
__global__ void __launch_bounds__(384) k_conv4(const float* __restrict__ cw,
                                               const float* __restrict__ cb) {
    int t = threadIdx.x;
    int c = (t % 96) * 4;
    int r0 = blockIdx.x * 32 + (t / 96) * 8;
    bool hist = (r0 & (LSEQ - 1)) != 0;
    float4 wA = *(const float4*)&cw[(c + 0) * 4];
    float4 wB = *(const float4*)&cw[(c + 1) * 4];
    float4 wC = *(const float4*)&cw[(c + 2) * 4];
    float4 wD = *(const float4*)&cw[(c + 3) * 4];
    float4 bias = *(const float4*)&cb[c];
    const float* src = g_zx + 256 + c;
    float* dst = g_xc + c;
    float4 z = make_float4(0.f, 0.f, 0.f, 0.f);
    float4 x0 = hist ? *(const float4*)&src[(size_t)(r0 - 3) * DPROJ] : z;
    float4 x1 = hist ? *(const float4*)&src[(size_t)(r0 - 2) * DPROJ] : z;
    float4 x2 = hist ? *(const float4*)&src[(size_t)(r0 - 1) * DPROJ] : z;
#pragma unroll
    for (int s = 0; s < 8; s++) {
        int r = r0 + s;
        float4 x3 = *(const float4*)&src[(size_t)r * DPROJ];
        float4 o;
        o.x = silu(bias.x + wA.x * x0.x + wA.y * x1.x + wA.z * x2.x + wA.w * x3.x);
        o.y = silu(bias.y + wB.x * x0.y + wB.y * x1.y + wB.z * x2.y + wB.w * x3.y);
        o.z = silu(bias.z + wC.x * x0.z + wC.y * x1.z + wC.z * x2.z + wC.w * x3.z);
        o.w = silu(bias.w + wD.x * x0.w + wD.y * x1.w + wD.z * x2.w + wD.w * x3.w);
        *(float4*)&dst[(size_t)r * CONVD] = o;
        x0 = x1; x1 = x2; x2 = x3;
    }
}

// ---------------- SSD pass A via HMMA bf16x3 --------------------------------
#define SA_BH 0
#define SA_BL 4608
#define SA_XH 9216
#define SA_XL 11776
#define SA_END 14336
__global__ void __launch_bounds__(256) k_ssd_a_mma(const float* __restrict__ A_log,
                                                   const float* __restrict__ dtb) {
    __shared__ __align__(16) __nv_bfloat16 smb[SA_END];
    __shared__ float sdt[64], sS[64], ssc[64];
    int tid = threadIdx.x;
    int cid = blockIdx.x;
    int bh = cid >> 6, c = cid & 63;
    int b = bh >> 3, h = bh & 7;
    int r0 = b * LSEQ + c * QC;
    float A = -__expf(A_log[h]);

    if (tid < 64) {
        float v = g_zx[(size_t)(r0 + tid) * DPROJ + 640 + h] + dtb[h];
        v = (v > 20.f) ? v : log1pf(__expf(v));
        sdt[tid] = v;
        g_dtb[(size_t)(r0 + tid) * NH + h] = v;
    }
    for (int i = tid; i < 1024; i += 256) {
        int s = i >> 4, q = (i & 15) * 4;
        float4 bv = *(const float4*)&g_xc[(size_t)(r0 + s) * CONVD + 256 + q];
        __nv_bfloat16 h4[4], l4[4];
        split4(bv, h4, l4);
        *(uint2*)&smb[SA_BH + s * 72 + q] = *(uint2*)h4;
        *(uint2*)&smb[SA_BL + s * 72 + q] = *(uint2*)l4;
    }
    __syncthreads();
    if (tid < 64) {
        float v = sdt[tid] * A;
#pragma unroll
        for (int o = 1; o < 32; o <<= 1) {
            float u = __shfl_up_sync(0xffffffffu, v, o);
            if ((tid & 31) >= o) v += u;
        }
        sS[tid] = v;
    }
    __syncthreads();
    if (tid >= 32 && tid < 64) sS[tid] += sS[31];
    __syncthreads();
    float T = sS[63];
    if (tid < 64) {
        float sv = sS[tid];
        g_S[(size_t)cid * QC + tid] = sv;
        ssc[tid] = __expf(T - sv) * sdt[tid];
    }
    if (tid == 0) g_T[cid] = T;
    __syncthreads();
    for (int i = tid; i < 512; i += 256) {
        int s = i >> 3, q = (i & 7) * 4;
        float4 v = *(const float4*)&g_xc[(size_t)(r0 + s) * CONVD + h * HD + q];
        float sc = ssc[s];
        v.x *= sc; v.y *= sc; v.z *= sc; v.w *= sc;
        __nv_bfloat16 h4[4], l4[4];
        split4(v, h4, l4);
        *(uint2*)&smb[SA_XH + s * 40 + q] = *(uint2*)h4;
        *(uint2*)&smb[SA_XL + s * 40 + q] = *(uint2*)l4;
    }
    __syncthreads();

    uint32_t sb = smem_u32(smb);
    int wid = tid >> 5, lane = tid & 31;
    int mw = wid & 1, nw = wid >> 1;
    int gidx = lane >> 3;
    int a_soff = (gidx >> 1) * 8, a_poff = (gidx & 1) * 8;
    int b_soff = ((lane >> 3) & 1) * 8, b_noff = (lane >> 4) * 8;
    float acc[2][4] = {};
#pragma unroll
    for (int kf = 0; kf < 4; kf++) {
        int k0 = kf << 4;
        uint32_t xh4[4], xl4[4], bh4[4], bl4[4];
        uint32_t ax = sb + (uint32_t)((SA_XH + (k0 + a_soff + (lane & 7)) * 40
                                       + mw * 16 + a_poff) * 2);
        LDSM4T(xh4, ax);
        LDSM4T(xl4, ax + (SA_XL - SA_XH) * 2);
        uint32_t bad = sb + (uint32_t)((SA_BH + (k0 + b_soff + (lane & 7)) * 72
                                        + nw * 16 + b_noff) * 2);
        LDSM4T(bh4, bad);
        LDSM4T(bl4, bad + (SA_BL - SA_BH) * 2);
#pragma unroll
        for (int nf = 0; nf < 2; nf++) {
            MMA16816(acc[nf], xh4, bh4[nf * 2], bh4[nf * 2 + 1]);
            MMA16816(acc[nf], xh4, bl4[nf * 2], bl4[nf * 2 + 1]);
            MMA16816(acc[nf], xl4, bh4[nf * 2], bh4[nf * 2 + 1]);
        }
    }
    int g = lane >> 2, tg = lane & 3;
    size_t ub = (size_t)cid * 2048;
#pragma unroll
    for (int nf = 0; nf < 2; nf++) {
        int p = mw * 16 + g, n = nw * 16 + nf * 8 + tg * 2;
        *(float2*)&g_U[ub + p * 64 + n]       = make_float2(acc[nf][0], acc[nf][1]);
        *(float2*)&g_U[ub + (p + 8) * 64 + n] = make_float2(acc[nf][2], acc[nf][3]);
    }
}

// ---------------- SSD pass B step 1: decay matrix W per (b,h) ---------------
// W[c][j] = (j<c) ? exp(I[c-1]-I[j]) : 0, I = inclusive prefix of T.
__global__ void k_ssd_w() {
    __shared__ float sI[64];
    int bh = blockIdx.x, tid = threadIdx.x;
    if (tid < 64) {
        float v = g_T[bh * 64 + tid];
#pragma unroll
        for (int o = 1; o < 32; o <<= 1) {
            float u = __shfl_up_sync(0xffffffffu, v, o);
            if ((tid & 31) >= o) v += u;
        }
        sI[tid] = v;
    }
    __syncthreads();
    if (tid >= 32 && tid < 64) sI[tid] += sI[31];
    __syncthreads();
    for (int i = tid; i < 4096; i += 256) {
        int c = i >> 6, j = i & 63;
        float w = (j < c) ? __expf(sI[c - 1] - sI[j]) : 0.f;
        __nv_bfloat16 h, l;
        split_bf16(w, h, l);
        g_wbh[(size_t)bh * 4096 + i] = h;
        g_wbl[(size_t)bh * 4096 + i] = l;
    }
}

// ---------------- SSD pass B step 2: hs = W @ U via HMMA bf16x3 -------------
#define SB_WH 0
#define SB_WL 4608
#define SB_UH 9216
#define SB_UL 13824
#define SB_END 18432
__global__ void __launch_bounds__(256) k_ssd_b_mma() {
    __shared__ __align__(16) __nv_bfloat16 smb[SB_END];
    int tid = threadIdx.x, wid = tid >> 5, lane = tid & 31;
    int bh = blockIdx.x;
    int col0 = blockIdx.y * 64;
    for (int i = tid; i < 512; i += 256) {
        int c = i >> 3, q = (i & 7) * 8;
        *(uint4*)&smb[SB_WH + c * 72 + q] =
            *(const uint4*)&g_wbh[(size_t)bh * 4096 + c * 64 + q];
        *(uint4*)&smb[SB_WL + c * 72 + q] =
            *(const uint4*)&g_wbl[(size_t)bh * 4096 + c * 64 + q];
    }
    for (int i = tid; i < 1024; i += 256) {
        int j = i >> 4, q = (i & 15) * 4;
        float4 v = *(const float4*)&g_U[((size_t)bh * 64 + j) * 2048 + col0 + q];
        __nv_bfloat16 h4[4], l4[4];
        split4(v, h4, l4);
        *(uint2*)&smb[SB_UH + j * 72 + q] = *(uint2*)h4;
        *(uint2*)&smb[SB_UL + j * 72 + q] = *(uint2*)l4;
    }
    __syncthreads();
    uint32_t sb = smem_u32(smb);
    int mw = wid & 3, nw = wid >> 2;
    int crow = mw * 16, ncol = nw * 32;
    int lrow = lane & 15, lk = (lane >> 4) << 3;
    int b_soff = ((lane >> 3) & 1) * 8, b_noff = (lane >> 4) * 8;
    float acc[4][4] = {};
#pragma unroll
    for (int kf = 0; kf < 4; kf++) {
        int k0 = kf << 4;
        uint32_t whf[4], wlf[4];
        uint32_t ad = sb + (uint32_t)((SB_WH + (crow + lrow) * 72 + k0 + lk) * 2);
        LDSM4(whf, ad);
        LDSM4(wlf, ad + (SB_WL - SB_WH) * 2);
        uint32_t uh[2][4], ul[2][4];
#pragma unroll
        for (int hf = 0; hf < 2; hf++) {
            uint32_t ad2 = sb + (uint32_t)((SB_UH + (k0 + b_soff + (lane & 7)) * 72
                                            + ncol + hf * 16 + b_noff) * 2);
            LDSM4T(uh[hf], ad2);
            LDSM4T(ul[hf], ad2 + (SB_UL - SB_UH) * 2);
        }
#pragma unroll
        for (int nf = 0; nf < 4; nf++) {
            uint32_t* BH = &uh[nf >> 1][(nf & 1) * 2];
            uint32_t* BL = &ul[nf >> 1][(nf & 1) * 2];
            MMA16816(acc[nf], whf, BH[0], BH[1]);
            MMA16816(acc[nf], whf, BL[0], BL[1]);
            MMA16816(acc[nf], wlf, BH[0], BH[1]);
        }
    }
    int g = lane >> 2, tg = lane & 3;
#pragma unroll
    for (int nf = 0; nf < 4; nf++) {
        int c = crow + g, col = col0 + ncol + nf * 8 + tg * 2;
        *(float2*)&g_hs[((size_t)bh * 64 + c) * 2048 + col] =
            make_float2(acc[nf][0], acc[nf][1]);
        *(float2*)&g_hs[((size_t)bh * 64 + c + 8) * 2048 + col] =
            make_float2(acc[nf][2], acc[nf][3]);
    }
}

// ---------------- SSD pass C via HMMA bf16x3 --------------------------------
#define SC_P  72
#define SC_CH 0
#define SC_CL 4608
#define SC_BH 9216     /* later reused as M hi */
#define SC_BL 13824    /* later reused as M lo */
#define SC_XH 18432    /* X (s,p) pitch 40 */
#define SC_XL 20992
#define SC_HH 23552    /* hs (p,n) pitch 72 */
#define SC_HL 25856
#define SC_END 28160
__global__ void __launch_bounds__(256, 2) k_ssd_c_mma(const float* __restrict__ Dp) {
    extern __shared__ __align__(16) __nv_bfloat16 smb[];
    float* Ssm = (float*)(smb + SC_END);
    float* dts = Ssm + 64;
    int tid = threadIdx.x, wid = tid >> 5, lane = tid & 31;
    int cid = blockIdx.x;
    int bh = cid >> 6, c = cid & 63;
    int b = bh >> 3, h = bh & 7;
    int r0 = b * LSEQ + c * QC;
    float Dh = Dp[h];

    for (int i = tid; i < 1024; i += 256) {
        int s = i >> 4, q = (i & 15) * 4;
        float4 cv = *(const float4*)&g_xc[(size_t)(r0 + s) * CONVD + 320 + q];
        float4 bv = *(const float4*)&g_xc[(size_t)(r0 + s) * CONVD + 256 + q];
        __nv_bfloat16 h4[4], l4[4];
        split4(cv, h4, l4);
        *(uint2*)&smb[SC_CH + s * SC_P + q] = *(uint2*)h4;
        *(uint2*)&smb[SC_CL + s * SC_P + q] = *(uint2*)l4;
        split4(bv, h4, l4);
        *(uint2*)&smb[SC_BH + s * SC_P + q] = *(uint2*)h4;
        *(uint2*)&smb[SC_BL + s * SC_P + q] = *(uint2*)l4;
    }
    for (int i = tid; i < 512; i += 256) {
        int s = i >> 3, q = (i & 7) * 4;
        float4 v = *(const float4*)&g_xc[(size_t)(r0 + s) * CONVD + h * HD + q];
        __nv_bfloat16 h4[4], l4[4];
        split4(v, h4, l4);
        *(uint2*)&smb[SC_XH + s * 40 + q] = *(uint2*)h4;
        *(uint2*)&smb[SC_XL + s * 40 + q] = *(uint2*)l4;
    }
    for (int i = tid; i < 512; i += 256) {
        int p = i >> 4, q = (i & 15) * 4;
        float4 v = *(const float4*)&g_hs[(size_t)cid * 2048 + p * 64 + q];
        __nv_bfloat16 h4[4], l4[4];
        split4(v, h4, l4);
        *(uint2*)&smb[SC_HH + p * SC_P + q] = *(uint2*)h4;
        *(uint2*)&smb[SC_HL + p * SC_P + q] = *(uint2*)l4;
    }
    if (tid < 64) {
        Ssm[tid] = g_S[(size_t)cid * QC + tid];
        dts[tid] = g_dtb[(size_t)(r0 + tid) * NH + h];
    }
    __syncthreads();

    uint32_t sb = smem_u32(smb);
    int mw = wid & 3, nw = wid >> 2;
    int arow = mw * 16;
    int lrow = lane & 15, lk = (lane >> 4) << 3;
    int brow = (lane & 7) + ((lane >> 4) & 1) * 8;
    int bk = ((lane >> 3) & 1) << 3;
    int b_soff = ((lane >> 3) & 1) * 8, b_noff = (lane >> 4) * 8;

    float accg[4][4] = {};
#pragma unroll
    for (int kf = 0; kf < 4; kf++) {
        int k0 = kf << 4;
        uint32_t ch[4], cl[4];
        uint32_t ad = sb + (uint32_t)(((arow + lrow) * SC_P + k0 + lk) * 2);
        LDSM4(ch, ad + SC_CH * 2);
        LDSM4(cl, ad + SC_CL * 2);
        uint32_t bh2[2][4], bl2[2][4];
#pragma unroll
        for (int ng = 0; ng < 2; ng++) {
            uint32_t ad2 = sb + (uint32_t)(((nw * 32 + ng * 16 + brow) * SC_P + k0 + bk) * 2);
            LDSM4(bh2[ng], ad2 + SC_BH * 2);
            LDSM4(bl2[ng], ad2 + SC_BL * 2);
        }
#pragma unroll
        for (int nf = 0; nf < 4; nf++) {
            uint32_t* BH = &bh2[nf >> 1][(nf & 1) * 2];
            uint32_t* BL = &bl2[nf >> 1][(nf & 1) * 2];
            MMA16816(accg[nf], ch, BH[0], BH[1]);
            MMA16816(accg[nf], ch, BL[0], BL[1]);
            MMA16816(accg[nf], cl, BH[0], BH[1]);
        }
    }
    __syncthreads();

    int g = lane >> 2, tg = lane & 3;
    int t0 = arow + g, t1 = arow + g + 8;
    float St0 = Ssm[t0], St1 = Ssm[t1];
#pragma unroll
    for (int nf = 0; nf < 4; nf++) {
#pragma unroll
        for (int e = 0; e < 2; e++) {
            int s = nw * 32 + nf * 8 + tg * 2 + e;
            float ds = dts[s], Ss = Ssm[s];
            float m0 = (s <= t0) ? accg[nf][e]     * __expf(St0 - Ss) * ds : 0.f;
            float m1 = (s <= t1) ? accg[nf][2 + e] * __expf(St1 - Ss) * ds : 0.f;
            __nv_bfloat16 hh0, ll0, hh1, ll1;
            split_bf16(m0, hh0, ll0);
            split_bf16(m1, hh1, ll1);
            smb[SC_BH + t0 * SC_P + s] = hh0;
            smb[SC_BL + t0 * SC_P + s] = ll0;
            smb[SC_BH + t1 * SC_P + s] = hh1;
            smb[SC_BL + t1 * SC_P + s] = ll1;
        }
    }
    __syncthreads();

    int pw = wid >> 2;
    int prow = pw * 16;
    float ayi[2][4] = {}, ayo[2][4] = {};
#pragma unroll
    for (int kf = 0; kf < 4; kf++) {
        int k0 = kf << 4;
        uint32_t ad = sb + (uint32_t)(((arow + lrow) * SC_P + k0 + lk) * 2);
        uint32_t mh[4], ml[4], ch[4], cl[4];
        LDSM4(mh, ad + SC_BH * 2);
        LDSM4(ml, ad + SC_BL * 2);
        LDSM4(ch, ad + SC_CH * 2);
        LDSM4(cl, ad + SC_CL * 2);
        uint32_t xh[4], xl[4], hh2[4], hl2[4];
        uint32_t adx = sb + (uint32_t)((SC_XH + (k0 + b_soff + (lane & 7)) * 40
                                        + prow + b_noff) * 2);
        LDSM4T(xh, adx);
        LDSM4T(xl, adx + (SC_XL - SC_XH) * 2);
        uint32_t adh = sb + (uint32_t)(((prow + brow) * SC_P + k0 + bk) * 2);
        LDSM4(hh2, adh + SC_HH * 2);
        LDSM4(hl2, adh + SC_HL * 2);
#pragma unroll
        for (int nf = 0; nf < 2; nf++) {
            uint32_t* XH = &xh[nf * 2];  uint32_t* XL = &xl[nf * 2];
            uint32_t* HH = &hh2[nf * 2]; uint32_t* HL = &hl2[nf * 2];
            MMA16816(ayi[nf], mh, XH[0], XH[1]);
            MMA16816(ayi[nf], mh, XL[0], XL[1]);
            MMA16816(ayi[nf], ml, XH[0], XH[1]);
            MMA16816(ayo[nf], ch, HH[0], HH[1]);
            MMA16816(ayo[nf], ch, HL[0], HL[1]);
            MMA16816(ayo[nf], cl, HH[0], HH[1]);
        }
    }

    float eS0 = __expf(St0), eS1 = __expf(St1);
#pragma unroll
    for (int nf = 0; nf < 2; nf++) {
        int p = prow + nf * 8 + tg * 2;
        float xv00 = __bfloat162float(smb[SC_XH + t0 * 40 + p])
                   + __bfloat162float(smb[SC_XL + t0 * 40 + p]);
        float xv01 = __bfloat162float(smb[SC_XH + t0 * 40 + p + 1])
                   + __bfloat162float(smb[SC_XL + t0 * 40 + p + 1]);
        float xv10 = __bfloat162float(smb[SC_XH + t1 * 40 + p])
                   + __bfloat162float(smb[SC_XL + t1 * 40 + p]);
        float xv11 = __bfloat162float(smb[SC_XH + t1 * 40 + p + 1])
                   + __bfloat162float(smb[SC_XL + t1 * 40 + p + 1]);
        *(float2*)&g_y[(size_t)(r0 + t0) * DINNER + h * HD + p] =
            make_float2(ayi[nf][0] + eS0 * ayo[nf][0] + Dh * xv00,
                        ayi[nf][1] + eS0 * ayo[nf][1] + Dh * xv01);
        *(float2*)&g_y[(size_t)(r0 + t1) * DINNER + h * HD + p] =
            make_float2(ayi[nf][2] + eS1 * ayo[nf][2] + Dh * xv10,
                        ayi[nf][3] + eS1 * ayo[nf][3] + Dh * xv11);
    }
}

// ---------------- K4a: gating + gated RMSNorm (warp/row) --------------------
__global__ void k_gate(const float* __restrict__ gw) {
    int r    = blockIdx.x * 8 + (threadIdx.x >> 5);
    int lane = threadIdx.x & 31;
    float4 y0 = *(const float4*)&g_y[(size_t)r * DINNER + lane * 4];
    float4 y1 = *(const float4*)&g_y[(size_t)r * DINNER + 128 + lane * 4];
    float4 z0 = *(const float4*)&g_zx[(size_t)r * DPROJ + lane * 4];
    float4 z1 = *(const float4*)&g_zx[(size_t)r * DPROJ + 128 + lane * 4];
    float gv[8];
    gv[0] = y0.x * silu(z0.x); gv[1] = y0.y * silu(z0.y);
    gv[2] = y0.z * silu(z0.z); gv[3] = y0.w * silu(z0.w);
    gv[4] = y1.x * silu(z1.x); gv[5] = y1.y * silu(z1.y);
    gv[6] = y1.z * silu(z1.z); gv[7] = y1.w * silu(z1.w);
    float ss = 0.f;
#pragma unroll
    for (int j = 0; j < 8; j++) ss += gv[j] * gv[j];
#pragma unroll
    for (int o = 16; o; o >>= 1) ss += __shfl_xor_sync(0xffffffffu, ss, o);
    float sc = rsqrtf(ss * (1.f / DINNER) + 1e-5f);
    float4 w0 = *(const float4*)&gw[lane * 4];
    float4 w1 = *(const float4*)&gw[128 + lane * 4];
    float wv[8] = {w0.x, w0.y, w0.z, w0.w, w1.x, w1.y, w1.z, w1.w};
    __nv_bfloat16 h[8], l[8];
#pragma unroll
    for (int j = 0; j < 8; j++) split_bf16(gv[j] * sc * wv[j], h[j], l[j]);
    *(uint2*)&g_gh[(size_t)r * DINNER + lane * 4]       = *(uint2*)&h[0];
    *(uint2*)&g_gh[(size_t)r * DINNER + 128 + lane * 4] = *(uint2*)&h[4];
    *(uint2*)&g_gl[(size_t)r * DINNER + lane * 4]       = *(uint2*)&l[0];
    *(uint2*)&g_gl[(size_t)r * DINNER + 128 + lane * 4] = *(uint2*)&l[4];
}

// ---------------- K4b: out_proj HMMA bf16x3 + residual ----------------------
#define OP_AH 0
#define OP_AL 17408
#define OP_BH 34816
#define OP_BL 52224
#define OP_TOT 69632
__global__ void __launch_bounds__(256, 1) k_outproj_mma(const float* __restrict__ x,
                                                        float* __restrict__ out) {
    extern __shared__ __align__(16) __nv_bfloat16 smb[];
    int tid = threadIdx.x, wid = tid >> 5, lane = tid & 31;
    int rowBase = blockIdx.x * 128;
    uint32_t sb = smem_u32(smb);
    int mw = wid & 3, nw = wid >> 2;
    int arow = mw * 32, ncol = nw * 64;
    float acc[2][8][4] = {};
    int lrow = lane & 15, lk = (lane >> 4) << 3;
    int brow = (lane & 7) + ((lane >> 4) & 1) * 8;
    int bk = ((lane >> 3) & 1) << 3;

    for (int kc = 0; kc < 2; kc++) {
        if (kc) __syncthreads();
        for (int i = tid; i < 2048; i += 256) {
            int r = i >> 4, c = (i & 15) << 3;
            size_t ao = (size_t)(rowBase + r) * DINNER + kc * 128 + c;
            *(uint4*)&smb[OP_AH + r * 136 + c] = *(const uint4*)(g_gh + ao);
            *(uint4*)&smb[OP_AL + r * 136 + c] = *(const uint4*)(g_gl + ao);
            size_t bo = (size_t)r * DINNER + kc * 128 + c;
            *(uint4*)&smb[OP_BH + r * 136 + c] = *(const uint4*)(g_woh + bo);
            *(uint4*)&smb[OP_BL + r * 136 + c] = *(const uint4*)(g_wol + bo);
        }
        __syncthreads();
#pragma unroll
        for (int kf = 0; kf < 8; kf++) {
            int k0 = kf << 4;
            uint32_t ah[2][4], al[2][4];
#pragma unroll
            for (int mi = 0; mi < 2; mi++) {
                uint32_t ad = sb + (uint32_t)(((arow + mi * 16 + lrow) * 136 + k0 + lk) * 2);
                LDSM4(ah[mi], ad + OP_AH * 2);
                LDSM4(al[mi], ad + OP_AL * 2);
            }
            uint32_t bh[4][4], bl[4][4];
#pragma unroll
            for (int ng = 0; ng < 4; ng++) {
                uint32_t ad = sb + (uint32_t)(((ncol + ng * 16 + brow) * 136 + k0 + bk) * 2);
                LDSM4(bh[ng], ad + OP_BH * 2);
                LDSM4(bl[ng], ad + OP_BL * 2);
            }
#pragma unroll
            for (int mi = 0; mi < 2; mi++)
#pragma unroll
                for (int nf = 0; nf < 8; nf++) {
                    uint32_t* BH = &bh[nf >> 1][(nf & 1) * 2];
                    uint32_t* BL = &bl[nf >> 1][(nf & 1) * 2];
                    MMA16816(acc[mi][nf], ah[mi], BH[0], BH[1]);
                    MMA16816(acc[mi][nf], ah[mi], BL[0], BL[1]);
                    MMA16816(acc[mi][nf], al[mi], BH[0], BH[1]);
                }
        }
    }
    int g = lane >> 2, tg = lane & 3;
#pragma unroll
    for (int mi = 0; mi < 2; mi++) {
        int r = rowBase + arow + mi * 16 + g;
#pragma unroll
        for (int nf = 0; nf < 8; nf++) {
            int c = ncol + nf * 8 + tg * 2;
            float2 x0 = *(const float2*)&x[(size_t)r * DMODEL + c];
            float2 x1 = *(const float2*)&x[(size_t)(r + 8) * DMODEL + c];
            *(float2*)&out[(size_t)r * DMODEL + c] =
                make_float2(acc[mi][nf][0] + x0.x, acc[mi][nf][1] + x0.y);
            *(float2*)&out[(size_t)(r + 8) * DMODEL + c] =
                make_float2(acc[mi][nf][2] + x1.x, acc[mi][nf][3] + x1.y);
        }
    }
}

extern "C" void kernel_launch(void* const* d_in, const int* in_sizes, int n_in,
                              void* d_out, int out_size) {
    const float* x          = (const float*)d_in[0];
    const float* norm_w     = (const float*)d_in[1];
    const float* in_proj_w  = (const float*)d_in[2];
    const float* conv_w     = (const float*)d_in[3];
    const float* conv_b     = (const float*)d_in[4];
    const float* dt_bias    = (const float*)d_in[5];
    const float* A_log      = (const float*)d_in[6];
    const float* D          = (const float*)d_in[7];
    const float* gnorm_w    = (const float*)d_in[8];
    const float* out_proj_w = (const float*)d_in[9];
    float* out = (float*)d_out;

    const int in_smem   = IP_TOT * 2;
    const int out_smem  = OP_TOT * 2;
    const int ssdc_smem = SC_END * 2 + 512;
    cudaFuncSetAttribute(k_inproj_mma,  cudaFuncAttributeMaxDynamicSharedMemorySize, in_smem);
    cudaFuncSetAttribute(k_outproj_mma, cudaFuncAttributeMaxDynamicSharedMemorySize, out_smem);
    cudaFuncSetAttribute(k_ssd_c_mma,   cudaFuncAttributeMaxDynamicSharedMemorySize, ssdc_smem);

    k_wsplit<<<113, 256>>>(in_proj_w, out_proj_w);
    k_rmsnorm<<<RTOT / 8, 256>>>(x, norm_w);
    k_inproj_mma<<<dim3(RTOT / 128, 7), 256, in_smem>>>();
    k_conv4<<<RTOT / 32, 384>>>(conv_w, conv_b);
    k_ssd_a_mma<<<NCID, 256>>>(A_log, dt_bias);
    k_ssd_w<<<NBATCH * NH, 256>>>();
    k_ssd_b_mma<<<dim3(NBATCH * NH, 32), 256>>>();
    k_ssd_c_mma<<<NCID, 256, ssdc_smem>>>(D);
    k_gate<<<RTOT / 8, 256>>>(gnorm_w);
    k_outproj_mma<<<RTOT / 128, 256, out_smem>>>(x, out);
}